// round 14
// baseline (speedup 1.0000x reference)
#include <cuda_runtime.h>

// VDEncoderDecoder: stacked LSTM encoder (8->32->8->1, T=48) + decoder
// (1->2->2->1, 60 steps) + fused fc via g = fc2_w @ fc1_w.
// Group of 64 batch elements per CTA, FOUR warps. Warp w owns e1 units
// [8w,8w+8) and e2 units [2w,2w+2); each lane processes TWO elements
// (eA = base+lane, eB = base+32+lane). Hidden state exchanged via smem +
// 2 syncthreads per timestep. Decoder on warps 0,1 (one element each);
// warps 2,3 run ahead into the next timestep's e1 (safe: H1B(t) is fully
// consumed into registers right after its sync). 2048 warps total vs 1024
// in R13 -> issue rate (the measured binder at 57%) rises.

#define TPB 128
static constexpr int BATCH = 32768;
static constexpr int T = 48;

// smem float offsets
static constexpr int OFF_W1IH = 0;       // 128x8   = 1024
static constexpr int OFF_W1HH = 1024;    // 128x32  = 4096
static constexpr int OFF_B1   = 5120;    // 128
static constexpr int OFF_W2IH = 5248;    // 32x32   = 1024
static constexpr int OFF_W2HH = 6272;    // 32x8    = 256
static constexpr int OFF_B2   = 6528;    // 32
static constexpr int OFF_W3IH = 6560;    // 32
static constexpr int OFF_W3HH = 6592;    // 4
static constexpr int OFF_B3   = 6596;    // 4
static constexpr int OFF_D1IH = 6600;    // 8
static constexpr int OFF_D1HH = 6608;    // 16
static constexpr int OFF_BD1  = 6624;    // 8
static constexpr int OFF_D2IH = 6632;    // 16
static constexpr int OFF_D2HH = 6648;    // 16
static constexpr int OFF_BD2  = 6664;    // 8
static constexpr int OFF_D3IH = 6672;    // 8
static constexpr int OFF_D3HH = 6680;    // 4
static constexpr int OFF_BD3  = 6684;    // 4
static constexpr int OFF_G    = 6688;    // 720
static constexpr int OFF_CB   = 7408;    // 12
static constexpr int OFF_H1B  = 7420;    // 32 units x 64 elems = 2048
static constexpr int OFF_H2B  = 9468;    // 8 units x 64 elems  = 512
static constexpr int SMEM_FLOATS = 9980; // 39.9 KB -> 3 CTAs/SM fits

__device__ __forceinline__ float sigf(float x) {
    return __fdividef(1.0f, 1.0f + __expf(-x));
}
__device__ __forceinline__ float tanhx(float x) {
    float e = __expf(2.0f * x);
    return 1.0f - __fdividef(2.0f, e + 1.0f);
}

// Small scalar LSTM cell (decoder path), fully unrolled.
template<int H, int DIN>
__device__ __forceinline__ void lstm_small(
    const float* __restrict__ wih, const float* __restrict__ whh,
    const float* __restrict__ bias,
    const float (&xin)[DIN], float (&h)[H], float (&c)[H])
{
    float hn[H];
#pragma unroll
    for (int u = 0; u < H; ++u) {
        float a0 = bias[u];
        float a1 = bias[H + u];
        float a2 = bias[2 * H + u];
        float a3 = bias[3 * H + u];
#pragma unroll
        for (int d = 0; d < DIN; ++d) {
            float xv = xin[d];
            a0 = fmaf(xv, wih[u * DIN + d], a0);
            a1 = fmaf(xv, wih[(H + u) * DIN + d], a1);
            a2 = fmaf(xv, wih[(2 * H + u) * DIN + d], a2);
            a3 = fmaf(xv, wih[(3 * H + u) * DIN + d], a3);
        }
#pragma unroll
        for (int j = 0; j < H; ++j) {
            float hv = h[j];
            a0 = fmaf(hv, whh[u * H + j], a0);
            a1 = fmaf(hv, whh[(H + u) * H + j], a1);
            a2 = fmaf(hv, whh[(2 * H + u) * H + j], a2);
            a3 = fmaf(hv, whh[(3 * H + u) * H + j], a3);
        }
        float ig = sigf(a0);
        float fg = sigf(a1);
        float gg = tanhx(a2);
        float og = sigf(a3);
        float cn = fmaf(fg, c[u], ig * gg);
        c[u] = cn;
        hn[u] = og * tanhx(cn);
    }
#pragma unroll
    for (int u = 0; u < H; ++u) h[u] = hn[u];
}

__global__ void __launch_bounds__(TPB, 3)
vd_encdec_kernel(
    const float* __restrict__ x,
    const float* __restrict__ w1ih, const float* __restrict__ w1hh, const float* __restrict__ b1,
    const float* __restrict__ w2ih, const float* __restrict__ w2hh, const float* __restrict__ b2,
    const float* __restrict__ w3ih, const float* __restrict__ w3hh, const float* __restrict__ b3,
    const float* __restrict__ d1ih, const float* __restrict__ d1hh, const float* __restrict__ bd1,
    const float* __restrict__ d2ih, const float* __restrict__ d2hh, const float* __restrict__ bd2,
    const float* __restrict__ d3ih, const float* __restrict__ d3hh, const float* __restrict__ bd3,
    const float* __restrict__ fc1w, const float* __restrict__ fc1b,
    const float* __restrict__ fc2w, const float* __restrict__ fc2b,
    float* __restrict__ out)
{
    __shared__ __align__(16) float sw[SMEM_FLOATS];
    const int tid = threadIdx.x;

    for (int i = tid; i < 1024; i += TPB) sw[OFF_W1IH + i] = w1ih[i];
    for (int i = tid; i < 4096; i += TPB) sw[OFF_W1HH + i] = w1hh[i];
    for (int i = tid; i < 128;  i += TPB) sw[OFF_B1   + i] = b1[i];
    for (int i = tid; i < 1024; i += TPB) sw[OFF_W2IH + i] = w2ih[i];
    for (int i = tid; i < 256;  i += TPB) sw[OFF_W2HH + i] = w2hh[i];
    for (int i = tid; i < 32;   i += TPB) sw[OFF_B2   + i] = b2[i];
    for (int i = tid; i < 32;   i += TPB) sw[OFF_W3IH + i] = w3ih[i];
    if (tid < 4)  sw[OFF_W3HH + tid] = w3hh[tid];
    if (tid < 4)  sw[OFF_B3   + tid] = b3[tid];
    if (tid < 8)  sw[OFF_D1IH + tid] = d1ih[tid];
    if (tid < 16) sw[OFF_D1HH + tid] = d1hh[tid];
    if (tid < 8)  sw[OFF_BD1 + tid] = bd1[tid];
    if (tid < 16) sw[OFF_D2IH + tid] = d2ih[tid];
    if (tid < 16) sw[OFF_D2HH + tid] = d2hh[tid];
    if (tid < 8)  sw[OFF_BD2 + tid] = bd2[tid];
    if (tid < 8)  sw[OFF_D3IH + tid] = d3ih[tid];
    if (tid < 4)  sw[OFF_D3HH + tid] = d3hh[tid];
    if (tid < 4)  sw[OFF_BD3 + tid] = bd3[tid];
    for (int i = tid; i < 720; i += TPB) {
        int t = i / 12, j = i % 12;
        float a = 0.0f;
        for (int k = 0; k < 32; ++k)
            a = fmaf(fc2w[j * 32 + k], fc1w[k * 60 + t], a);
        sw[OFF_G + i] = a;
    }
    if (tid < 12) {
        float a = fc2b[tid];
        for (int k = 0; k < 32; ++k)
            a = fmaf(fc2w[tid * 32 + k], fc1b[k], a);
        sw[OFF_CB + tid] = a;
    }
    __syncthreads();

    const int lane = tid & 31;
    const int wq = tid >> 5;              // 0..3
    const int base = blockIdx.x * 64;
    const int eA = base + lane;
    const int eB = base + 32 + lane;
    const float* xA = x + (size_t)eA * (T * 8);
    const float* xB = x + (size_t)eB * (T * 8);
    const int ub1 = wq * 8;               // my e1 units: ub1..ub1+7
    const int ub2 = wq * 2;               // my e2 units: ub2..ub2+1

    float h1A[32], h1B[32];               // full old h1 (registers)
    float c1A[8], c1B[8];                 // my units' c
    float h2A[8], h2B[8];
    float c2A[2], c2B[2];
    float h3[1], c3[1];
    float hd1[2], cd1[2], hd2[2], cd2[2], hd3[1], cd3[1];
    float acc[12];

#pragma unroll
    for (int i = 0; i < 32; ++i) { h1A[i] = 0.0f; h1B[i] = 0.0f; }
#pragma unroll
    for (int i = 0; i < 8; ++i) { c1A[i] = 0.0f; c1B[i] = 0.0f; h2A[i] = 0.0f; h2B[i] = 0.0f; }
#pragma unroll
    for (int i = 0; i < 2; ++i) { c2A[i] = 0.0f; c2B[i] = 0.0f; }
    h3[0] = 0.0f; c3[0] = 0.0f;
#pragma unroll
    for (int i = 0; i < 2; ++i) { hd1[i] = 0.0f; cd1[i] = 0.0f; hd2[i] = 0.0f; cd2[i] = 0.0f; }
    hd3[0] = 0.0f; cd3[0] = 0.0f;
#pragma unroll
    for (int i = 0; i < 12; ++i) acc[i] = 0.0f;

    // ---- fused steps t = 0..47 ----
#pragma unroll 1
    for (int t = 0; t < T; ++t) {
        float4 qa = *reinterpret_cast<const float4*>(xA + t * 8);
        float4 qb = *reinterpret_cast<const float4*>(xA + t * 8 + 4);
        float xrA[8] = { qa.x, qa.y, qa.z, qa.w, qb.x, qb.y, qb.z, qb.w };
        float4 ra = *reinterpret_cast<const float4*>(xB + t * 8);
        float4 rb = *reinterpret_cast<const float4*>(xB + t * 8 + 4);
        float xrB[8] = { ra.x, ra.y, ra.z, ra.w, rb.x, rb.y, rb.z, rb.w };

        // ---- e1: my 8 units, both elements ----
#pragma unroll 1
        for (int uu = 0; uu < 8; ++uu) {
            int u = ub1 + uu;
            float b0 = sw[OFF_B1 + u];
            float b1v = sw[OFF_B1 + 32 + u];
            float b2v = sw[OFF_B1 + 64 + u];
            float b3v = sw[OFF_B1 + 96 + u];
            float a0A = b0, a1A = b1v, a2A = b2v, a3A = b3v;
            float a0B = b0, a1B = b1v, a2B = b2v, a3B = b3v;
            const float4* w0 = reinterpret_cast<const float4*>(sw + OFF_W1IH + u * 8);
            const float4* w1 = reinterpret_cast<const float4*>(sw + OFF_W1IH + (32 + u) * 8);
            const float4* w2 = reinterpret_cast<const float4*>(sw + OFF_W1IH + (64 + u) * 8);
            const float4* w3 = reinterpret_cast<const float4*>(sw + OFF_W1IH + (96 + u) * 8);
#pragma unroll
            for (int d = 0; d < 2; ++d) {
                float4 q0 = w0[d], q1 = w1[d], q2 = w2[d], q3 = w3[d];
                float pA0 = xrA[4 * d + 0], pA1 = xrA[4 * d + 1];
                float pA2 = xrA[4 * d + 2], pA3 = xrA[4 * d + 3];
                float pB0 = xrB[4 * d + 0], pB1 = xrB[4 * d + 1];
                float pB2 = xrB[4 * d + 2], pB3 = xrB[4 * d + 3];
                a0A = fmaf(pA0, q0.x, a0A); a0B = fmaf(pB0, q0.x, a0B);
                a1A = fmaf(pA0, q1.x, a1A); a1B = fmaf(pB0, q1.x, a1B);
                a2A = fmaf(pA0, q2.x, a2A); a2B = fmaf(pB0, q2.x, a2B);
                a3A = fmaf(pA0, q3.x, a3A); a3B = fmaf(pB0, q3.x, a3B);
                a0A = fmaf(pA1, q0.y, a0A); a0B = fmaf(pB1, q0.y, a0B);
                a1A = fmaf(pA1, q1.y, a1A); a1B = fmaf(pB1, q1.y, a1B);
                a2A = fmaf(pA1, q2.y, a2A); a2B = fmaf(pB1, q2.y, a2B);
                a3A = fmaf(pA1, q3.y, a3A); a3B = fmaf(pB1, q3.y, a3B);
                a0A = fmaf(pA2, q0.z, a0A); a0B = fmaf(pB2, q0.z, a0B);
                a1A = fmaf(pA2, q1.z, a1A); a1B = fmaf(pB2, q1.z, a1B);
                a2A = fmaf(pA2, q2.z, a2A); a2B = fmaf(pB2, q2.z, a2B);
                a3A = fmaf(pA2, q3.z, a3A); a3B = fmaf(pB2, q3.z, a3B);
                a0A = fmaf(pA3, q0.w, a0A); a0B = fmaf(pB3, q0.w, a0B);
                a1A = fmaf(pA3, q1.w, a1A); a1B = fmaf(pB3, q1.w, a1B);
                a2A = fmaf(pA3, q2.w, a2A); a2B = fmaf(pB3, q2.w, a2B);
                a3A = fmaf(pA3, q3.w, a3A); a3B = fmaf(pB3, q3.w, a3B);
            }
            const float4* v0 = reinterpret_cast<const float4*>(sw + OFF_W1HH + u * 32);
            const float4* v1 = reinterpret_cast<const float4*>(sw + OFF_W1HH + (32 + u) * 32);
            const float4* v2 = reinterpret_cast<const float4*>(sw + OFF_W1HH + (64 + u) * 32);
            const float4* v3 = reinterpret_cast<const float4*>(sw + OFF_W1HH + (96 + u) * 32);
#pragma unroll
            for (int j = 0; j < 8; ++j) {
                float4 q0 = v0[j], q1 = v1[j], q2 = v2[j], q3 = v3[j];
                float pA0 = h1A[4 * j + 0], pA1 = h1A[4 * j + 1];
                float pA2 = h1A[4 * j + 2], pA3 = h1A[4 * j + 3];
                float pB0 = h1B[4 * j + 0], pB1 = h1B[4 * j + 1];
                float pB2 = h1B[4 * j + 2], pB3 = h1B[4 * j + 3];
                a0A = fmaf(pA0, q0.x, a0A); a0B = fmaf(pB0, q0.x, a0B);
                a1A = fmaf(pA0, q1.x, a1A); a1B = fmaf(pB0, q1.x, a1B);
                a2A = fmaf(pA0, q2.x, a2A); a2B = fmaf(pB0, q2.x, a2B);
                a3A = fmaf(pA0, q3.x, a3A); a3B = fmaf(pB0, q3.x, a3B);
                a0A = fmaf(pA1, q0.y, a0A); a0B = fmaf(pB1, q0.y, a0B);
                a1A = fmaf(pA1, q1.y, a1A); a1B = fmaf(pB1, q1.y, a1B);
                a2A = fmaf(pA1, q2.y, a2A); a2B = fmaf(pB1, q2.y, a2B);
                a3A = fmaf(pA1, q3.y, a3A); a3B = fmaf(pB1, q3.y, a3B);
                a0A = fmaf(pA2, q0.z, a0A); a0B = fmaf(pB2, q0.z, a0B);
                a1A = fmaf(pA2, q1.z, a1A); a1B = fmaf(pB2, q1.z, a1B);
                a2A = fmaf(pA2, q2.z, a2A); a2B = fmaf(pB2, q2.z, a2B);
                a3A = fmaf(pA2, q3.z, a3A); a3B = fmaf(pB2, q3.z, a3B);
                a0A = fmaf(pA3, q0.w, a0A); a0B = fmaf(pB3, q0.w, a0B);
                a1A = fmaf(pA3, q1.w, a1A); a1B = fmaf(pB3, q1.w, a1B);
                a2A = fmaf(pA3, q2.w, a2A); a2B = fmaf(pB3, q2.w, a2B);
                a3A = fmaf(pA3, q3.w, a3A); a3B = fmaf(pB3, q3.w, a3B);
            }
            {
                float ig = sigf(a0A), fg = sigf(a1A), gg = tanhx(a2A), og = sigf(a3A);
                float cn = fmaf(fg, c1A[uu], ig * gg);
                c1A[uu] = cn;
                sw[OFF_H1B + u * 64 + lane] = og * tanhx(cn);
            }
            {
                float ig = sigf(a0B), fg = sigf(a1B), gg = tanhx(a2B), og = sigf(a3B);
                float cn = fmaf(fg, c1B[uu], ig * gg);
                c1B[uu] = cn;
                sw[OFF_H1B + u * 64 + 32 + lane] = og * tanhx(cn);
            }
        }
        __syncthreads();
#pragma unroll
        for (int j = 0; j < 32; ++j) {
            h1A[j] = sw[OFF_H1B + j * 64 + lane];
            h1B[j] = sw[OFF_H1B + j * 64 + 32 + lane];
        }

        // ---- e2: my 2 units, both elements ----
#pragma unroll
        for (int uu = 0; uu < 2; ++uu) {
            int u = ub2 + uu;
            float b0 = sw[OFF_B2 + u];
            float b1v = sw[OFF_B2 + 8 + u];
            float b2v = sw[OFF_B2 + 16 + u];
            float b3v = sw[OFF_B2 + 24 + u];
            float a0A = b0, a1A = b1v, a2A = b2v, a3A = b3v;
            float a0B = b0, a1B = b1v, a2B = b2v, a3B = b3v;
            const float4* w0 = reinterpret_cast<const float4*>(sw + OFF_W2IH + u * 32);
            const float4* w1 = reinterpret_cast<const float4*>(sw + OFF_W2IH + (8 + u) * 32);
            const float4* w2 = reinterpret_cast<const float4*>(sw + OFF_W2IH + (16 + u) * 32);
            const float4* w3 = reinterpret_cast<const float4*>(sw + OFF_W2IH + (24 + u) * 32);
#pragma unroll
            for (int d = 0; d < 8; ++d) {
                float4 q0 = w0[d], q1 = w1[d], q2 = w2[d], q3 = w3[d];
                float pA0 = h1A[4 * d + 0], pA1 = h1A[4 * d + 1];
                float pA2 = h1A[4 * d + 2], pA3 = h1A[4 * d + 3];
                float pB0 = h1B[4 * d + 0], pB1 = h1B[4 * d + 1];
                float pB2 = h1B[4 * d + 2], pB3 = h1B[4 * d + 3];
                a0A = fmaf(pA0, q0.x, a0A); a0B = fmaf(pB0, q0.x, a0B);
                a1A = fmaf(pA0, q1.x, a1A); a1B = fmaf(pB0, q1.x, a1B);
                a2A = fmaf(pA0, q2.x, a2A); a2B = fmaf(pB0, q2.x, a2B);
                a3A = fmaf(pA0, q3.x, a3A); a3B = fmaf(pB0, q3.x, a3B);
                a0A = fmaf(pA1, q0.y, a0A); a0B = fmaf(pB1, q0.y, a0B);
                a1A = fmaf(pA1, q1.y, a1A); a1B = fmaf(pB1, q1.y, a1B);
                a2A = fmaf(pA1, q2.y, a2A); a2B = fmaf(pB1, q2.y, a2B);
                a3A = fmaf(pA1, q3.y, a3A); a3B = fmaf(pB1, q3.y, a3B);
                a0A = fmaf(pA2, q0.z, a0A); a0B = fmaf(pB2, q0.z, a0B);
                a1A = fmaf(pA2, q1.z, a1A); a1B = fmaf(pB2, q1.z, a1B);
                a2A = fmaf(pA2, q2.z, a2A); a2B = fmaf(pB2, q2.z, a2B);
                a3A = fmaf(pA2, q3.z, a3A); a3B = fmaf(pB2, q3.z, a3B);
                a0A = fmaf(pA3, q0.w, a0A); a0B = fmaf(pB3, q0.w, a0B);
                a1A = fmaf(pA3, q1.w, a1A); a1B = fmaf(pB3, q1.w, a1B);
                a2A = fmaf(pA3, q2.w, a2A); a2B = fmaf(pB3, q2.w, a2B);
                a3A = fmaf(pA3, q3.w, a3A); a3B = fmaf(pB3, q3.w, a3B);
            }
            const float4* v0 = reinterpret_cast<const float4*>(sw + OFF_W2HH + u * 8);
            const float4* v1 = reinterpret_cast<const float4*>(sw + OFF_W2HH + (8 + u) * 8);
            const float4* v2 = reinterpret_cast<const float4*>(sw + OFF_W2HH + (16 + u) * 8);
            const float4* v3 = reinterpret_cast<const float4*>(sw + OFF_W2HH + (24 + u) * 8);
#pragma unroll
            for (int j = 0; j < 2; ++j) {
                float4 q0 = v0[j], q1 = v1[j], q2 = v2[j], q3 = v3[j];
                float pA0 = h2A[4 * j + 0], pA1 = h2A[4 * j + 1];
                float pA2 = h2A[4 * j + 2], pA3 = h2A[4 * j + 3];
                float pB0 = h2B[4 * j + 0], pB1 = h2B[4 * j + 1];
                float pB2 = h2B[4 * j + 2], pB3 = h2B[4 * j + 3];
                a0A = fmaf(pA0, q0.x, a0A); a0B = fmaf(pB0, q0.x, a0B);
                a1A = fmaf(pA0, q1.x, a1A); a1B = fmaf(pB0, q1.x, a1B);
                a2A = fmaf(pA0, q2.x, a2A); a2B = fmaf(pB0, q2.x, a2B);
                a3A = fmaf(pA0, q3.x, a3A); a3B = fmaf(pB0, q3.x, a3B);
                a0A = fmaf(pA1, q0.y, a0A); a0B = fmaf(pB1, q0.y, a0B);
                a1A = fmaf(pA1, q1.y, a1A); a1B = fmaf(pB1, q1.y, a1B);
                a2A = fmaf(pA1, q2.y, a2A); a2B = fmaf(pB1, q2.y, a2B);
                a3A = fmaf(pA1, q3.y, a3A); a3B = fmaf(pB1, q3.y, a3B);
                a0A = fmaf(pA2, q0.z, a0A); a0B = fmaf(pB2, q0.z, a0B);
                a1A = fmaf(pA2, q1.z, a1A); a1B = fmaf(pB2, q1.z, a1B);
                a2A = fmaf(pA2, q2.z, a2A); a2B = fmaf(pB2, q2.z, a2B);
                a3A = fmaf(pA2, q3.z, a3A); a3B = fmaf(pB2, q3.z, a3B);
                a0A = fmaf(pA3, q0.w, a0A); a0B = fmaf(pB3, q0.w, a0B);
                a1A = fmaf(pA3, q1.w, a1A); a1B = fmaf(pB3, q1.w, a1B);
                a2A = fmaf(pA3, q2.w, a2A); a2B = fmaf(pB3, q2.w, a2B);
                a3A = fmaf(pA3, q3.w, a3A); a3B = fmaf(pB3, q3.w, a3B);
            }
            {
                float ig = sigf(a0A), fg = sigf(a1A), gg = tanhx(a2A), og = sigf(a3A);
                float cn = fmaf(fg, c2A[uu], ig * gg);
                c2A[uu] = cn;
                sw[OFF_H2B + u * 64 + lane] = og * tanhx(cn);
            }
            {
                float ig = sigf(a0B), fg = sigf(a1B), gg = tanhx(a2B), og = sigf(a3B);
                float cn = fmaf(fg, c2B[uu], ig * gg);
                c2B[uu] = cn;
                sw[OFF_H2B + u * 64 + 32 + lane] = og * tanhx(cn);
            }
        }
        __syncthreads();
#pragma unroll
        for (int j = 0; j < 8; ++j) {
            h2A[j] = sw[OFF_H2B + j * 64 + lane];
            h2B[j] = sw[OFF_H2B + j * 64 + 32 + lane];
        }

        // ---- decoder: warp0 -> element A, warp1 -> element B; warps 2,3 run ahead ----
        if (wq < 2) {
            float h2d[8];
#pragma unroll
            for (int j = 0; j < 8; ++j) h2d[j] = (wq == 0) ? h2A[j] : h2B[j];
            lstm_small<1, 8>(sw + OFF_W3IH, sw + OFF_W3HH, sw + OFF_B3, h2d, h3, c3);
            float dv[1] = { h3[0] };
            lstm_small<2, 1>(sw + OFF_D1IH, sw + OFF_D1HH, sw + OFF_BD1, dv, hd1, cd1);
            lstm_small<2, 2>(sw + OFF_D2IH, sw + OFF_D2HH, sw + OFF_BD2, hd1, hd2, cd2);
            lstm_small<1, 2>(sw + OFF_D3IH, sw + OFF_D3HH, sw + OFF_BD3, hd2, hd3, cd3);
            float y = hd3[0];
            const float* gr = sw + OFF_G + t * 12;
#pragma unroll
            for (int j = 0; j < 12; ++j) acc[j] = fmaf(y, gr[j], acc[j]);
        }
    }

    // ---- aux steps + epilogue: warps 0,1 only ----
    if (wq < 2) {
        const int eD = base + 32 * wq + lane;
        const float* xD = x + (size_t)eD * (T * 8);
#pragma unroll 1
        for (int t = T; t < 60; ++t) {
            float dv[1] = { xD[(t - 12) * 8 + 4] };
            lstm_small<2, 1>(sw + OFF_D1IH, sw + OFF_D1HH, sw + OFF_BD1, dv, hd1, cd1);
            lstm_small<2, 2>(sw + OFF_D2IH, sw + OFF_D2HH, sw + OFF_BD2, hd1, hd2, cd2);
            lstm_small<1, 2>(sw + OFF_D3IH, sw + OFF_D3HH, sw + OFF_BD3, hd2, hd3, cd3);
            float y = hd3[0];
            const float* gr = sw + OFF_G + t * 12;
#pragma unroll
            for (int j = 0; j < 12; ++j) acc[j] = fmaf(y, gr[j], acc[j]);
        }
        float r[12];
#pragma unroll
        for (int j = 0; j < 12; ++j) r[j] = acc[j] + sw[OFF_CB + j];
        float4* op = reinterpret_cast<float4*>(out + (size_t)eD * 12);
        op[0] = make_float4(r[0], r[1], r[2], r[3]);
        op[1] = make_float4(r[4], r[5], r[6], r[7]);
        op[2] = make_float4(r[8], r[9], r[10], r[11]);
    }
}

extern "C" void kernel_launch(void* const* d_in, const int* in_sizes, int n_in,
                              void* d_out, int out_size) {
    (void)in_sizes; (void)n_in; (void)out_size;
    const float* x    = (const float*)d_in[0];
    const float* w1ih = (const float*)d_in[1];
    const float* w1hh = (const float*)d_in[2];
    const float* b1   = (const float*)d_in[3];
    const float* w2ih = (const float*)d_in[4];
    const float* w2hh = (const float*)d_in[5];
    const float* b2   = (const float*)d_in[6];
    const float* w3ih = (const float*)d_in[7];
    const float* w3hh = (const float*)d_in[8];
    const float* b3   = (const float*)d_in[9];
    const float* d1ih = (const float*)d_in[10];
    const float* d1hh = (const float*)d_in[11];
    const float* bd1  = (const float*)d_in[12];
    const float* d2ih = (const float*)d_in[13];
    const float* d2hh = (const float*)d_in[14];
    const float* bd2  = (const float*)d_in[15];
    const float* d3ih = (const float*)d_in[16];
    const float* d3hh = (const float*)d_in[17];
    const float* bd3  = (const float*)d_in[18];
    const float* fc1w = (const float*)d_in[19];
    const float* fc1b = (const float*)d_in[20];
    const float* fc2w = (const float*)d_in[21];
    const float* fc2b = (const float*)d_in[22];
    float* out = (float*)d_out;

    dim3 grid(BATCH / 64);   // 64 elements, 4 warps per CTA
    dim3 block(TPB);
    vd_encdec_kernel<<<grid, block>>>(
        x, w1ih, w1hh, b1, w2ih, w2hh, b2, w3ih, w3hh, b3,
        d1ih, d1hh, bd1, d2ih, d2hh, bd2, d3ih, d3hh, bd3,
        fc1w, fc1b, fc2w, fc2b, out);
}

// round 15
// speedup vs baseline: 1.2096x; 1.2096x over previous
#include <cuda_runtime.h>

// VDEncoderDecoder: stacked LSTM encoder (8->32->8->1, T=48) + decoder
// (1->2->2->1, 60 steps) + fused fc via g = fc2_w @ fc1_w.
// R13 structure (group of 64 elements per CTA, 2 warps; warp h owns e1 units
// [16h,16h+16) and e2 units [4h,4h+4); each lane processes 2 elements) with
// single-MUFU activations: tanh.approx.f32 directly, sigmoid via
// 0.5*tanh(x/2)+0.5. Halves MUFU count and cuts the per-unit serial
// activation tail ~2x (R13 was latency-bound: issue 57%, nothing saturated).

#define TPB 64
static constexpr int BATCH = 32768;
static constexpr int T = 48;

// smem float offsets
static constexpr int OFF_W1IH = 0;       // 128x8   = 1024
static constexpr int OFF_W1HH = 1024;    // 128x32  = 4096
static constexpr int OFF_B1   = 5120;    // 128
static constexpr int OFF_W2IH = 5248;    // 32x32   = 1024
static constexpr int OFF_W2HH = 6272;    // 32x8    = 256
static constexpr int OFF_B2   = 6528;    // 32
static constexpr int OFF_W3IH = 6560;    // 32
static constexpr int OFF_W3HH = 6592;    // 4
static constexpr int OFF_B3   = 6596;    // 4
static constexpr int OFF_D1IH = 6600;    // 8
static constexpr int OFF_D1HH = 6608;    // 16
static constexpr int OFF_BD1  = 6624;    // 8
static constexpr int OFF_D2IH = 6632;    // 16
static constexpr int OFF_D2HH = 6648;    // 16
static constexpr int OFF_BD2  = 6664;    // 8
static constexpr int OFF_D3IH = 6672;    // 8
static constexpr int OFF_D3HH = 6680;    // 4
static constexpr int OFF_BD3  = 6684;    // 4
static constexpr int OFF_G    = 6688;    // 720
static constexpr int OFF_CB   = 7408;    // 12
static constexpr int OFF_H1B  = 7420;    // 32 units x 64 elems = 2048
static constexpr int OFF_H2B  = 9468;    // 8 units x 64 elems  = 512
static constexpr int SMEM_FLOATS = 9980; // 39.9 KB

__device__ __forceinline__ float tanha(float x) {
    float y;
    asm("tanh.approx.f32 %0, %1;" : "=f"(y) : "f"(x));
    return y;
}
__device__ __forceinline__ float sigf(float x) {
    // sigmoid(x) = 0.5 * tanh(x/2) + 0.5  (1 MUFU + 2 FMA)
    return fmaf(tanha(0.5f * x), 0.5f, 0.5f);
}
__device__ __forceinline__ float tanhx(float x) {
    return tanha(x);
}

// Small scalar LSTM cell (decoder path), fully unrolled.
template<int H, int DIN>
__device__ __forceinline__ void lstm_small(
    const float* __restrict__ wih, const float* __restrict__ whh,
    const float* __restrict__ bias,
    const float (&xin)[DIN], float (&h)[H], float (&c)[H])
{
    float hn[H];
#pragma unroll
    for (int u = 0; u < H; ++u) {
        float a0 = bias[u];
        float a1 = bias[H + u];
        float a2 = bias[2 * H + u];
        float a3 = bias[3 * H + u];
#pragma unroll
        for (int d = 0; d < DIN; ++d) {
            float xv = xin[d];
            a0 = fmaf(xv, wih[u * DIN + d], a0);
            a1 = fmaf(xv, wih[(H + u) * DIN + d], a1);
            a2 = fmaf(xv, wih[(2 * H + u) * DIN + d], a2);
            a3 = fmaf(xv, wih[(3 * H + u) * DIN + d], a3);
        }
#pragma unroll
        for (int j = 0; j < H; ++j) {
            float hv = h[j];
            a0 = fmaf(hv, whh[u * H + j], a0);
            a1 = fmaf(hv, whh[(H + u) * H + j], a1);
            a2 = fmaf(hv, whh[(2 * H + u) * H + j], a2);
            a3 = fmaf(hv, whh[(3 * H + u) * H + j], a3);
        }
        float ig = sigf(a0);
        float fg = sigf(a1);
        float gg = tanhx(a2);
        float og = sigf(a3);
        float cn = fmaf(fg, c[u], ig * gg);
        c[u] = cn;
        hn[u] = og * tanhx(cn);
    }
#pragma unroll
    for (int u = 0; u < H; ++u) h[u] = hn[u];
}

__global__ void __launch_bounds__(TPB)
vd_encdec_kernel(
    const float* __restrict__ x,
    const float* __restrict__ w1ih, const float* __restrict__ w1hh, const float* __restrict__ b1,
    const float* __restrict__ w2ih, const float* __restrict__ w2hh, const float* __restrict__ b2,
    const float* __restrict__ w3ih, const float* __restrict__ w3hh, const float* __restrict__ b3,
    const float* __restrict__ d1ih, const float* __restrict__ d1hh, const float* __restrict__ bd1,
    const float* __restrict__ d2ih, const float* __restrict__ d2hh, const float* __restrict__ bd2,
    const float* __restrict__ d3ih, const float* __restrict__ d3hh, const float* __restrict__ bd3,
    const float* __restrict__ fc1w, const float* __restrict__ fc1b,
    const float* __restrict__ fc2w, const float* __restrict__ fc2b,
    float* __restrict__ out)
{
    __shared__ __align__(16) float sw[SMEM_FLOATS];
    const int tid = threadIdx.x;

    for (int i = tid; i < 1024; i += TPB) sw[OFF_W1IH + i] = w1ih[i];
    for (int i = tid; i < 4096; i += TPB) sw[OFF_W1HH + i] = w1hh[i];
    for (int i = tid; i < 128;  i += TPB) sw[OFF_B1   + i] = b1[i];
    for (int i = tid; i < 1024; i += TPB) sw[OFF_W2IH + i] = w2ih[i];
    for (int i = tid; i < 256;  i += TPB) sw[OFF_W2HH + i] = w2hh[i];
    for (int i = tid; i < 32;   i += TPB) sw[OFF_B2   + i] = b2[i];
    for (int i = tid; i < 32;   i += TPB) sw[OFF_W3IH + i] = w3ih[i];
    if (tid < 4)  sw[OFF_W3HH + tid] = w3hh[tid];
    if (tid < 4)  sw[OFF_B3   + tid] = b3[tid];
    if (tid < 8)  sw[OFF_D1IH + tid] = d1ih[tid];
    if (tid < 16) sw[OFF_D1HH + tid] = d1hh[tid];
    if (tid < 8)  sw[OFF_BD1 + tid] = bd1[tid];
    if (tid < 16) sw[OFF_D2IH + tid] = d2ih[tid];
    if (tid < 16) sw[OFF_D2HH + tid] = d2hh[tid];
    if (tid < 8)  sw[OFF_BD2 + tid] = bd2[tid];
    if (tid < 8)  sw[OFF_D3IH + tid] = d3ih[tid];
    if (tid < 4)  sw[OFF_D3HH + tid] = d3hh[tid];
    if (tid < 4)  sw[OFF_BD3 + tid] = bd3[tid];
    for (int i = tid; i < 720; i += TPB) {
        int t = i / 12, j = i % 12;
        float a = 0.0f;
        for (int k = 0; k < 32; ++k)
            a = fmaf(fc2w[j * 32 + k], fc1w[k * 60 + t], a);
        sw[OFF_G + i] = a;
    }
    if (tid < 12) {
        float a = fc2b[tid];
        for (int k = 0; k < 32; ++k)
            a = fmaf(fc2w[tid * 32 + k], fc1b[k], a);
        sw[OFF_CB + tid] = a;
    }
    __syncthreads();

    const int lane = tid & 31;
    const int half = tid >> 5;
    const int base = blockIdx.x * 64;
    const int eA = base + lane;
    const int eB = base + 32 + lane;
    const int eD = base + 32 * half + lane;   // my decoder element
    const float* xA = x + (size_t)eA * (T * 8);
    const float* xB = x + (size_t)eB * (T * 8);
    const float* xD = x + (size_t)eD * (T * 8);
    const int ub1 = half * 16;
    const int ub2 = half * 4;

    float h1A[32], h1B[32];        // full old h1 (registers, static idx)
    float c1A[16], c1B[16];        // my units' c
    float h2A[8], h2B[8];
    float c2A[4], c2B[4];
    float h3[1], c3[1];
    float hd1[2], cd1[2], hd2[2], cd2[2], hd3[1], cd3[1];
    float acc[12];

#pragma unroll
    for (int i = 0; i < 32; ++i) { h1A[i] = 0.0f; h1B[i] = 0.0f; }
#pragma unroll
    for (int i = 0; i < 16; ++i) { c1A[i] = 0.0f; c1B[i] = 0.0f; }
#pragma unroll
    for (int i = 0; i < 8; ++i) { h2A[i] = 0.0f; h2B[i] = 0.0f; }
#pragma unroll
    for (int i = 0; i < 4; ++i) { c2A[i] = 0.0f; c2B[i] = 0.0f; }
    h3[0] = 0.0f; c3[0] = 0.0f;
#pragma unroll
    for (int i = 0; i < 2; ++i) { hd1[i] = 0.0f; cd1[i] = 0.0f; hd2[i] = 0.0f; cd2[i] = 0.0f; }
    hd3[0] = 0.0f; cd3[0] = 0.0f;
#pragma unroll
    for (int i = 0; i < 12; ++i) acc[i] = 0.0f;

    // ---- fused steps t = 0..47 ----
#pragma unroll 1
    for (int t = 0; t < T; ++t) {
        float4 qa = *reinterpret_cast<const float4*>(xA + t * 8);
        float4 qb = *reinterpret_cast<const float4*>(xA + t * 8 + 4);
        float xrA[8] = { qa.x, qa.y, qa.z, qa.w, qb.x, qb.y, qb.z, qb.w };
        float4 ra = *reinterpret_cast<const float4*>(xB + t * 8);
        float4 rb = *reinterpret_cast<const float4*>(xB + t * 8 + 4);
        float xrB[8] = { ra.x, ra.y, ra.z, ra.w, rb.x, rb.y, rb.z, rb.w };

        // ---- e1: my 16 units, both elements ----
#pragma unroll 1
        for (int uu = 0; uu < 16; ++uu) {
            int u = ub1 + uu;
            float b0 = sw[OFF_B1 + u];
            float b1v = sw[OFF_B1 + 32 + u];
            float b2v = sw[OFF_B1 + 64 + u];
            float b3v = sw[OFF_B1 + 96 + u];
            float a0A = b0, a1A = b1v, a2A = b2v, a3A = b3v;
            float a0B = b0, a1B = b1v, a2B = b2v, a3B = b3v;
            const float4* w0 = reinterpret_cast<const float4*>(sw + OFF_W1IH + u * 8);
            const float4* w1 = reinterpret_cast<const float4*>(sw + OFF_W1IH + (32 + u) * 8);
            const float4* w2 = reinterpret_cast<const float4*>(sw + OFF_W1IH + (64 + u) * 8);
            const float4* w3 = reinterpret_cast<const float4*>(sw + OFF_W1IH + (96 + u) * 8);
#pragma unroll
            for (int d = 0; d < 2; ++d) {
                float4 q0 = w0[d], q1 = w1[d], q2 = w2[d], q3 = w3[d];
                float pA0 = xrA[4 * d + 0], pA1 = xrA[4 * d + 1];
                float pA2 = xrA[4 * d + 2], pA3 = xrA[4 * d + 3];
                float pB0 = xrB[4 * d + 0], pB1 = xrB[4 * d + 1];
                float pB2 = xrB[4 * d + 2], pB3 = xrB[4 * d + 3];
                a0A = fmaf(pA0, q0.x, a0A); a0B = fmaf(pB0, q0.x, a0B);
                a1A = fmaf(pA0, q1.x, a1A); a1B = fmaf(pB0, q1.x, a1B);
                a2A = fmaf(pA0, q2.x, a2A); a2B = fmaf(pB0, q2.x, a2B);
                a3A = fmaf(pA0, q3.x, a3A); a3B = fmaf(pB0, q3.x, a3B);
                a0A = fmaf(pA1, q0.y, a0A); a0B = fmaf(pB1, q0.y, a0B);
                a1A = fmaf(pA1, q1.y, a1A); a1B = fmaf(pB1, q1.y, a1B);
                a2A = fmaf(pA1, q2.y, a2A); a2B = fmaf(pB1, q2.y, a2B);
                a3A = fmaf(pA1, q3.y, a3A); a3B = fmaf(pB1, q3.y, a3B);
                a0A = fmaf(pA2, q0.z, a0A); a0B = fmaf(pB2, q0.z, a0B);
                a1A = fmaf(pA2, q1.z, a1A); a1B = fmaf(pB2, q1.z, a1B);
                a2A = fmaf(pA2, q2.z, a2A); a2B = fmaf(pB2, q2.z, a2B);
                a3A = fmaf(pA2, q3.z, a3A); a3B = fmaf(pB2, q3.z, a3B);
                a0A = fmaf(pA3, q0.w, a0A); a0B = fmaf(pB3, q0.w, a0B);
                a1A = fmaf(pA3, q1.w, a1A); a1B = fmaf(pB3, q1.w, a1B);
                a2A = fmaf(pA3, q2.w, a2A); a2B = fmaf(pB3, q2.w, a2B);
                a3A = fmaf(pA3, q3.w, a3A); a3B = fmaf(pB3, q3.w, a3B);
            }
            const float4* v0 = reinterpret_cast<const float4*>(sw + OFF_W1HH + u * 32);
            const float4* v1 = reinterpret_cast<const float4*>(sw + OFF_W1HH + (32 + u) * 32);
            const float4* v2 = reinterpret_cast<const float4*>(sw + OFF_W1HH + (64 + u) * 32);
            const float4* v3 = reinterpret_cast<const float4*>(sw + OFF_W1HH + (96 + u) * 32);
#pragma unroll
            for (int j = 0; j < 8; ++j) {
                float4 q0 = v0[j], q1 = v1[j], q2 = v2[j], q3 = v3[j];
                float pA0 = h1A[4 * j + 0], pA1 = h1A[4 * j + 1];
                float pA2 = h1A[4 * j + 2], pA3 = h1A[4 * j + 3];
                float pB0 = h1B[4 * j + 0], pB1 = h1B[4 * j + 1];
                float pB2 = h1B[4 * j + 2], pB3 = h1B[4 * j + 3];
                a0A = fmaf(pA0, q0.x, a0A); a0B = fmaf(pB0, q0.x, a0B);
                a1A = fmaf(pA0, q1.x, a1A); a1B = fmaf(pB0, q1.x, a1B);
                a2A = fmaf(pA0, q2.x, a2A); a2B = fmaf(pB0, q2.x, a2B);
                a3A = fmaf(pA0, q3.x, a3A); a3B = fmaf(pB0, q3.x, a3B);
                a0A = fmaf(pA1, q0.y, a0A); a0B = fmaf(pB1, q0.y, a0B);
                a1A = fmaf(pA1, q1.y, a1A); a1B = fmaf(pB1, q1.y, a1B);
                a2A = fmaf(pA1, q2.y, a2A); a2B = fmaf(pB1, q2.y, a2B);
                a3A = fmaf(pA1, q3.y, a3A); a3B = fmaf(pB1, q3.y, a3B);
                a0A = fmaf(pA2, q0.z, a0A); a0B = fmaf(pB2, q0.z, a0B);
                a1A = fmaf(pA2, q1.z, a1A); a1B = fmaf(pB2, q1.z, a1B);
                a2A = fmaf(pA2, q2.z, a2A); a2B = fmaf(pB2, q2.z, a2B);
                a3A = fmaf(pA2, q3.z, a3A); a3B = fmaf(pB2, q3.z, a3B);
                a0A = fmaf(pA3, q0.w, a0A); a0B = fmaf(pB3, q0.w, a0B);
                a1A = fmaf(pA3, q1.w, a1A); a1B = fmaf(pB3, q1.w, a1B);
                a2A = fmaf(pA3, q2.w, a2A); a2B = fmaf(pB3, q2.w, a2B);
                a3A = fmaf(pA3, q3.w, a3A); a3B = fmaf(pB3, q3.w, a3B);
            }
            {
                float ig = sigf(a0A), fg = sigf(a1A), gg = tanhx(a2A), og = sigf(a3A);
                float cn = fmaf(fg, c1A[uu], ig * gg);
                c1A[uu] = cn;
                sw[OFF_H1B + u * 64 + lane] = og * tanhx(cn);
            }
            {
                float ig = sigf(a0B), fg = sigf(a1B), gg = tanhx(a2B), og = sigf(a3B);
                float cn = fmaf(fg, c1B[uu], ig * gg);
                c1B[uu] = cn;
                sw[OFF_H1B + u * 64 + 32 + lane] = og * tanhx(cn);
            }
        }
        __syncthreads();
#pragma unroll
        for (int j = 0; j < 32; ++j) {
            h1A[j] = sw[OFF_H1B + j * 64 + lane];
            h1B[j] = sw[OFF_H1B + j * 64 + 32 + lane];
        }

        // ---- e2: my 4 units, both elements ----
#pragma unroll 1
        for (int uu = 0; uu < 4; ++uu) {
            int u = ub2 + uu;
            float b0 = sw[OFF_B2 + u];
            float b1v = sw[OFF_B2 + 8 + u];
            float b2v = sw[OFF_B2 + 16 + u];
            float b3v = sw[OFF_B2 + 24 + u];
            float a0A = b0, a1A = b1v, a2A = b2v, a3A = b3v;
            float a0B = b0, a1B = b1v, a2B = b2v, a3B = b3v;
            const float4* w0 = reinterpret_cast<const float4*>(sw + OFF_W2IH + u * 32);
            const float4* w1 = reinterpret_cast<const float4*>(sw + OFF_W2IH + (8 + u) * 32);
            const float4* w2 = reinterpret_cast<const float4*>(sw + OFF_W2IH + (16 + u) * 32);
            const float4* w3 = reinterpret_cast<const float4*>(sw + OFF_W2IH + (24 + u) * 32);
#pragma unroll
            for (int d = 0; d < 8; ++d) {
                float4 q0 = w0[d], q1 = w1[d], q2 = w2[d], q3 = w3[d];
                float pA0 = h1A[4 * d + 0], pA1 = h1A[4 * d + 1];
                float pA2 = h1A[4 * d + 2], pA3 = h1A[4 * d + 3];
                float pB0 = h1B[4 * d + 0], pB1 = h1B[4 * d + 1];
                float pB2 = h1B[4 * d + 2], pB3 = h1B[4 * d + 3];
                a0A = fmaf(pA0, q0.x, a0A); a0B = fmaf(pB0, q0.x, a0B);
                a1A = fmaf(pA0, q1.x, a1A); a1B = fmaf(pB0, q1.x, a1B);
                a2A = fmaf(pA0, q2.x, a2A); a2B = fmaf(pB0, q2.x, a2B);
                a3A = fmaf(pA0, q3.x, a3A); a3B = fmaf(pB0, q3.x, a3B);
                a0A = fmaf(pA1, q0.y, a0A); a0B = fmaf(pB1, q0.y, a0B);
                a1A = fmaf(pA1, q1.y, a1A); a1B = fmaf(pB1, q1.y, a1B);
                a2A = fmaf(pA1, q2.y, a2A); a2B = fmaf(pB1, q2.y, a2B);
                a3A = fmaf(pA1, q3.y, a3A); a3B = fmaf(pB1, q3.y, a3B);
                a0A = fmaf(pA2, q0.z, a0A); a0B = fmaf(pB2, q0.z, a0B);
                a1A = fmaf(pA2, q1.z, a1A); a1B = fmaf(pB2, q1.z, a1B);
                a2A = fmaf(pA2, q2.z, a2A); a2B = fmaf(pB2, q2.z, a2B);
                a3A = fmaf(pA2, q3.z, a3A); a3B = fmaf(pB2, q3.z, a3B);
                a0A = fmaf(pA3, q0.w, a0A); a0B = fmaf(pB3, q0.w, a0B);
                a1A = fmaf(pA3, q1.w, a1A); a1B = fmaf(pB3, q1.w, a1B);
                a2A = fmaf(pA3, q2.w, a2A); a2B = fmaf(pB3, q2.w, a2B);
                a3A = fmaf(pA3, q3.w, a3A); a3B = fmaf(pB3, q3.w, a3B);
            }
            const float4* v0 = reinterpret_cast<const float4*>(sw + OFF_W2HH + u * 8);
            const float4* v1 = reinterpret_cast<const float4*>(sw + OFF_W2HH + (8 + u) * 8);
            const float4* v2 = reinterpret_cast<const float4*>(sw + OFF_W2HH + (16 + u) * 8);
            const float4* v3 = reinterpret_cast<const float4*>(sw + OFF_W2HH + (24 + u) * 8);
#pragma unroll
            for (int j = 0; j < 2; ++j) {
                float4 q0 = v0[j], q1 = v1[j], q2 = v2[j], q3 = v3[j];
                float pA0 = h2A[4 * j + 0], pA1 = h2A[4 * j + 1];
                float pA2 = h2A[4 * j + 2], pA3 = h2A[4 * j + 3];
                float pB0 = h2B[4 * j + 0], pB1 = h2B[4 * j + 1];
                float pB2 = h2B[4 * j + 2], pB3 = h2B[4 * j + 3];
                a0A = fmaf(pA0, q0.x, a0A); a0B = fmaf(pB0, q0.x, a0B);
                a1A = fmaf(pA0, q1.x, a1A); a1B = fmaf(pB0, q1.x, a1B);
                a2A = fmaf(pA0, q2.x, a2A); a2B = fmaf(pB0, q2.x, a2B);
                a3A = fmaf(pA0, q3.x, a3A); a3B = fmaf(pB0, q3.x, a3B);
                a0A = fmaf(pA1, q0.y, a0A); a0B = fmaf(pB1, q0.y, a0B);
                a1A = fmaf(pA1, q1.y, a1A); a1B = fmaf(pB1, q1.y, a1B);
                a2A = fmaf(pA1, q2.y, a2A); a2B = fmaf(pB1, q2.y, a2B);
                a3A = fmaf(pA1, q3.y, a3A); a3B = fmaf(pB1, q3.y, a3B);
                a0A = fmaf(pA2, q0.z, a0A); a0B = fmaf(pB2, q0.z, a0B);
                a1A = fmaf(pA2, q1.z, a1A); a1B = fmaf(pB2, q1.z, a1B);
                a2A = fmaf(pA2, q2.z, a2A); a2B = fmaf(pB2, q2.z, a2B);
                a3A = fmaf(pA2, q3.z, a3A); a3B = fmaf(pB2, q3.z, a3B);
                a0A = fmaf(pA3, q0.w, a0A); a0B = fmaf(pB3, q0.w, a0B);
                a1A = fmaf(pA3, q1.w, a1A); a1B = fmaf(pB3, q1.w, a1B);
                a2A = fmaf(pA3, q2.w, a2A); a2B = fmaf(pB3, q2.w, a2B);
                a3A = fmaf(pA3, q3.w, a3A); a3B = fmaf(pB3, q3.w, a3B);
            }
            {
                float ig = sigf(a0A), fg = sigf(a1A), gg = tanhx(a2A), og = sigf(a3A);
                float cn = fmaf(fg, c2A[uu], ig * gg);
                c2A[uu] = cn;
                sw[OFF_H2B + u * 64 + lane] = og * tanhx(cn);
            }
            {
                float ig = sigf(a0B), fg = sigf(a1B), gg = tanhx(a2B), og = sigf(a3B);
                float cn = fmaf(fg, c2B[uu], ig * gg);
                c2B[uu] = cn;
                sw[OFF_H2B + u * 64 + 32 + lane] = og * tanhx(cn);
            }
        }
        __syncthreads();
#pragma unroll
        for (int j = 0; j < 8; ++j) {
            h2A[j] = sw[OFF_H2B + j * 64 + lane];
            h2B[j] = sw[OFF_H2B + j * 64 + 32 + lane];
        }

        // ---- decoder: warp0 -> element A, warp1 -> element B ----
        float h2d[8];
#pragma unroll
        for (int j = 0; j < 8; ++j) h2d[j] = (half == 0) ? h2A[j] : h2B[j];
        lstm_small<1, 8>(sw + OFF_W3IH, sw + OFF_W3HH, sw + OFF_B3, h2d, h3, c3);
        float dv[1] = { h3[0] };
        lstm_small<2, 1>(sw + OFF_D1IH, sw + OFF_D1HH, sw + OFF_BD1, dv, hd1, cd1);
        lstm_small<2, 2>(sw + OFF_D2IH, sw + OFF_D2HH, sw + OFF_BD2, hd1, hd2, cd2);
        lstm_small<1, 2>(sw + OFF_D3IH, sw + OFF_D3HH, sw + OFF_BD3, hd2, hd3, cd3);
        float y = hd3[0];
        const float* gr = sw + OFF_G + t * 12;
#pragma unroll
        for (int j = 0; j < 12; ++j) acc[j] = fmaf(y, gr[j], acc[j]);
    }

    // ---- aux steps t = 48..59: decoder input = x[eD, t-12, 4] ----
#pragma unroll 1
    for (int t = T; t < 60; ++t) {
        float dv[1] = { xD[(t - 12) * 8 + 4] };
        lstm_small<2, 1>(sw + OFF_D1IH, sw + OFF_D1HH, sw + OFF_BD1, dv, hd1, cd1);
        lstm_small<2, 2>(sw + OFF_D2IH, sw + OFF_D2HH, sw + OFF_BD2, hd1, hd2, cd2);
        lstm_small<1, 2>(sw + OFF_D3IH, sw + OFF_D3HH, sw + OFF_BD3, hd2, hd3, cd3);
        float y = hd3[0];
        const float* gr = sw + OFF_G + t * 12;
#pragma unroll
        for (int j = 0; j < 12; ++j) acc[j] = fmaf(y, gr[j], acc[j]);
    }

    // ---- epilogue: out[eD] ----
    float r[12];
#pragma unroll
    for (int j = 0; j < 12; ++j) r[j] = acc[j] + sw[OFF_CB + j];
    float4* op = reinterpret_cast<float4*>(out + (size_t)eD * 12);
    op[0] = make_float4(r[0], r[1], r[2], r[3]);
    op[1] = make_float4(r[4], r[5], r[6], r[7]);
    op[2] = make_float4(r[8], r[9], r[10], r[11]);
}

extern "C" void kernel_launch(void* const* d_in, const int* in_sizes, int n_in,
                              void* d_out, int out_size) {
    (void)in_sizes; (void)n_in; (void)out_size;
    const float* x    = (const float*)d_in[0];
    const float* w1ih = (const float*)d_in[1];
    const float* w1hh = (const float*)d_in[2];
    const float* b1   = (const float*)d_in[3];
    const float* w2ih = (const float*)d_in[4];
    const float* w2hh = (const float*)d_in[5];
    const float* b2   = (const float*)d_in[6];
    const float* w3ih = (const float*)d_in[7];
    const float* w3hh = (const float*)d_in[8];
    const float* b3   = (const float*)d_in[9];
    const float* d1ih = (const float*)d_in[10];
    const float* d1hh = (const float*)d_in[11];
    const float* bd1  = (const float*)d_in[12];
    const float* d2ih = (const float*)d_in[13];
    const float* d2hh = (const float*)d_in[14];
    const float* bd2  = (const float*)d_in[15];
    const float* d3ih = (const float*)d_in[16];
    const float* d3hh = (const float*)d_in[17];
    const float* bd3  = (const float*)d_in[18];
    const float* fc1w = (const float*)d_in[19];
    const float* fc1b = (const float*)d_in[20];
    const float* fc2w = (const float*)d_in[21];
    const float* fc2b = (const float*)d_in[22];
    float* out = (float*)d_out;

    dim3 grid(BATCH / 64);   // 64 elements (2 warps) per CTA
    dim3 block(TPB);
    vd_encdec_kernel<<<grid, block>>>(
        x, w1ih, w1hh, b1, w2ih, w2hh, b2, w3ih, w3hh, b3,
        d1ih, d1hh, bd1, d2ih, d2hh, bd2, d3ih, d3hh, bd3,
        fc1w, fc1b, fc2w, fc2b, out);
}

// round 16
// speedup vs baseline: 1.3889x; 1.1482x over previous
#include <cuda_runtime.h>

// VDEncoderDecoder: stacked LSTM encoder (8->32->8->1, T=48) + decoder
// (1->2->2->1, 60 steps) + fused fc via g = fc2_w @ fc1_w.
// R15 structure (64 elements/CTA, 2 warps; warp h owns half the units; each
// lane runs 2 elements) + gate-pair fma.rn.f32x2: weights stored in smem as
// u64 PAIRS (w_i,w_f)/(w_g,w_o) -- two different weights per u64, so smem
// bytes are unchanged -- and the shared x/h multiplicand is splat once per
// use pair. Cuts ~21% of issue slots (the measured binder) with fma-pipe
// time and smem bytes flat. H-exchange buffers packed as float2.

#define TPB 64
static constexpr int BATCH = 32768;
static constexpr int T = 48;

typedef unsigned long long u64;

// u64 smem offsets (gate-pair weights)
static constexpr int P1IH_IF = 0;     // [u*8+d]  u=0..31   256
static constexpr int P1IH_GO = 256;   // 256
static constexpr int P1HH_IF = 512;   // [u*32+j]          1024
static constexpr int P1HH_GO = 1536;  // 1024
static constexpr int P2IH_IF = 2560;  // [u*32+d] u=0..7    256
static constexpr int P2IH_GO = 2816;  // 256
static constexpr int P2HH_IF = 3072;  // [u*8+j]            64
static constexpr int P2HH_GO = 3136;  // 64
static constexpr int PB1_IF  = 3200;  // 32
static constexpr int PB1_GO  = 3232;  // 32
static constexpr int PB2_IF  = 3264;  // 8
static constexpr int PB2_GO  = 3272;  // 8
static constexpr int U_TOTAL = 3280;  // 26240 B

// float smem offsets
static constexpr int S_W3IH = 0;     // 32
static constexpr int S_W3HH = 32;    // 4
static constexpr int S_B3   = 36;    // 4
static constexpr int S_D1IH = 40;    // 8
static constexpr int S_D1HH = 48;    // 16
static constexpr int S_BD1  = 64;    // 8
static constexpr int S_D2IH = 72;    // 16
static constexpr int S_D2HH = 88;    // 16
static constexpr int S_BD2  = 104;   // 8
static constexpr int S_D3IH = 112;   // 8
static constexpr int S_D3HH = 120;   // 4
static constexpr int S_BD3  = 124;   // 4
static constexpr int S_G    = 128;   // 720
static constexpr int S_CB   = 848;   // 12
static constexpr int S_H1B  = 860;   // 32 units x 32 lanes x 2 = 2048 (float2)
static constexpr int S_H2B  = 2908;  // 8 x 32 x 2 = 512 (float2)
static constexpr int F_TOTAL = 3420; // 13680 B ; total smem ~39.9 KB

__device__ __forceinline__ u64 fma2(u64 a, u64 b, u64 c) {
    u64 d;
    asm("fma.rn.f32x2 %0, %1, %2, %3;" : "=l"(d) : "l"(a), "l"(b), "l"(c));
    return d;
}
__device__ __forceinline__ u64 pack2(float v) {
    u64 r;
    asm("mov.b64 %0, {%1, %1};" : "=l"(r) : "f"(v));
    return r;
}
__device__ __forceinline__ u64 pack2f(float lo, float hi) {
    u64 r;
    asm("mov.b64 %0, {%1, %2};" : "=l"(r) : "f"(lo), "f"(hi));
    return r;
}
__device__ __forceinline__ void unpack2(u64 v, float& lo, float& hi) {
    asm("mov.b64 {%0, %1}, %2;" : "=f"(lo), "=f"(hi) : "l"(v));
}

__device__ __forceinline__ float tanha(float x) {
    float y;
    asm("tanh.approx.f32 %0, %1;" : "=f"(y) : "f"(x));
    return y;
}
__device__ __forceinline__ float sigf(float x) {
    return fmaf(tanha(0.5f * x), 0.5f, 0.5f);
}

// Small scalar LSTM cell (decoder path), fully unrolled.
template<int H, int DIN>
__device__ __forceinline__ void lstm_small(
    const float* __restrict__ wih, const float* __restrict__ whh,
    const float* __restrict__ bias,
    const float (&xin)[DIN], float (&h)[H], float (&c)[H])
{
    float hn[H];
#pragma unroll
    for (int u = 0; u < H; ++u) {
        float a0 = bias[u];
        float a1 = bias[H + u];
        float a2 = bias[2 * H + u];
        float a3 = bias[3 * H + u];
#pragma unroll
        for (int d = 0; d < DIN; ++d) {
            float xv = xin[d];
            a0 = fmaf(xv, wih[u * DIN + d], a0);
            a1 = fmaf(xv, wih[(H + u) * DIN + d], a1);
            a2 = fmaf(xv, wih[(2 * H + u) * DIN + d], a2);
            a3 = fmaf(xv, wih[(3 * H + u) * DIN + d], a3);
        }
#pragma unroll
        for (int j = 0; j < H; ++j) {
            float hv = h[j];
            a0 = fmaf(hv, whh[u * H + j], a0);
            a1 = fmaf(hv, whh[(H + u) * H + j], a1);
            a2 = fmaf(hv, whh[(2 * H + u) * H + j], a2);
            a3 = fmaf(hv, whh[(3 * H + u) * H + j], a3);
        }
        float ig = sigf(a0);
        float fg = sigf(a1);
        float gg = tanha(a2);
        float og = sigf(a3);
        float cn = fmaf(fg, c[u], ig * gg);
        c[u] = cn;
        hn[u] = og * tanha(cn);
    }
#pragma unroll
    for (int u = 0; u < H; ++u) h[u] = hn[u];
}

__global__ void __launch_bounds__(TPB)
vd_encdec_kernel(
    const float* __restrict__ x,
    const float* __restrict__ w1ih, const float* __restrict__ w1hh, const float* __restrict__ b1,
    const float* __restrict__ w2ih, const float* __restrict__ w2hh, const float* __restrict__ b2,
    const float* __restrict__ w3ih, const float* __restrict__ w3hh, const float* __restrict__ b3,
    const float* __restrict__ d1ih, const float* __restrict__ d1hh, const float* __restrict__ bd1,
    const float* __restrict__ d2ih, const float* __restrict__ d2hh, const float* __restrict__ bd2,
    const float* __restrict__ d3ih, const float* __restrict__ d3hh, const float* __restrict__ bd3,
    const float* __restrict__ fc1w, const float* __restrict__ fc1b,
    const float* __restrict__ fc2w, const float* __restrict__ fc2b,
    float* __restrict__ out)
{
    __shared__ __align__(16) u64 swp[U_TOTAL];
    __shared__ __align__(16) float swf[F_TOTAL];
    const int tid = threadIdx.x;

    // ---- stage gate-pair weights ----
    for (int i = tid; i < 256; i += TPB) {
        int u = i >> 3, d = i & 7;
        swp[P1IH_IF + i] = pack2f(w1ih[u * 8 + d], w1ih[(32 + u) * 8 + d]);
        swp[P1IH_GO + i] = pack2f(w1ih[(64 + u) * 8 + d], w1ih[(96 + u) * 8 + d]);
    }
    for (int i = tid; i < 1024; i += TPB) {
        int u = i >> 5, j = i & 31;
        swp[P1HH_IF + i] = pack2f(w1hh[u * 32 + j], w1hh[(32 + u) * 32 + j]);
        swp[P1HH_GO + i] = pack2f(w1hh[(64 + u) * 32 + j], w1hh[(96 + u) * 32 + j]);
    }
    for (int i = tid; i < 256; i += TPB) {
        int u = i >> 5, d = i & 31;
        swp[P2IH_IF + i] = pack2f(w2ih[u * 32 + d], w2ih[(8 + u) * 32 + d]);
        swp[P2IH_GO + i] = pack2f(w2ih[(16 + u) * 32 + d], w2ih[(24 + u) * 32 + d]);
    }
    for (int i = tid; i < 64; i += TPB) {
        int u = i >> 3, j = i & 7;
        swp[P2HH_IF + i] = pack2f(w2hh[u * 8 + j], w2hh[(8 + u) * 8 + j]);
        swp[P2HH_GO + i] = pack2f(w2hh[(16 + u) * 8 + j], w2hh[(24 + u) * 8 + j]);
    }
    for (int i = tid; i < 32; i += TPB) {
        swp[PB1_IF + i] = pack2f(b1[i], b1[32 + i]);
        swp[PB1_GO + i] = pack2f(b1[64 + i], b1[96 + i]);
    }
    if (tid < 8) {
        swp[PB2_IF + tid] = pack2f(b2[tid], b2[8 + tid]);
        swp[PB2_GO + tid] = pack2f(b2[16 + tid], b2[24 + tid]);
    }
    // small layers + fused fc
    for (int i = tid; i < 32; i += TPB) swf[S_W3IH + i] = w3ih[i];
    if (tid < 4)  swf[S_W3HH + tid] = w3hh[tid];
    if (tid < 4)  swf[S_B3 + tid] = b3[tid];
    if (tid < 8)  swf[S_D1IH + tid] = d1ih[tid];
    if (tid < 16) swf[S_D1HH + tid] = d1hh[tid];
    if (tid < 8)  swf[S_BD1 + tid] = bd1[tid];
    if (tid < 16) swf[S_D2IH + tid] = d2ih[tid];
    if (tid < 16) swf[S_D2HH + tid] = d2hh[tid];
    if (tid < 8)  swf[S_BD2 + tid] = bd2[tid];
    if (tid < 8)  swf[S_D3IH + tid] = d3ih[tid];
    if (tid < 4)  swf[S_D3HH + tid] = d3hh[tid];
    if (tid < 4)  swf[S_BD3 + tid] = bd3[tid];
    for (int i = tid; i < 720; i += TPB) {
        int t = i / 12, j = i % 12;
        float a = 0.0f;
        for (int k = 0; k < 32; ++k)
            a = fmaf(fc2w[j * 32 + k], fc1w[k * 60 + t], a);
        swf[S_G + i] = a;
    }
    if (tid < 12) {
        float a = fc2b[tid];
        for (int k = 0; k < 32; ++k)
            a = fmaf(fc2w[tid * 32 + k], fc1b[k], a);
        swf[S_CB + tid] = a;
    }
    __syncthreads();

    const int lane = tid & 31;
    const int half = tid >> 5;
    const int base = blockIdx.x * 64;
    const int eA = base + lane;
    const int eB = base + 32 + lane;
    const int eD = base + 32 * half + lane;
    const float* xA = x + (size_t)eA * (T * 8);
    const float* xB = x + (size_t)eB * (T * 8);
    const float* xD = x + (size_t)eD * (T * 8);
    const int ub1 = half * 16;
    const int ub2 = half * 4;

    float h1A[32], h1B[32];
    float c1A[16], c1B[16];
    float h2A[8], h2B[8];
    float c2A[4], c2B[4];
    float h3[1], c3[1];
    float hd1[2], cd1[2], hd2[2], cd2[2], hd3[1], cd3[1];
    float acc[12];

#pragma unroll
    for (int i = 0; i < 32; ++i) { h1A[i] = 0.0f; h1B[i] = 0.0f; }
#pragma unroll
    for (int i = 0; i < 16; ++i) { c1A[i] = 0.0f; c1B[i] = 0.0f; }
#pragma unroll
    for (int i = 0; i < 8; ++i) { h2A[i] = 0.0f; h2B[i] = 0.0f; }
#pragma unroll
    for (int i = 0; i < 4; ++i) { c2A[i] = 0.0f; c2B[i] = 0.0f; }
    h3[0] = 0.0f; c3[0] = 0.0f;
#pragma unroll
    for (int i = 0; i < 2; ++i) { hd1[i] = 0.0f; cd1[i] = 0.0f; hd2[i] = 0.0f; cd2[i] = 0.0f; }
    hd3[0] = 0.0f; cd3[0] = 0.0f;
#pragma unroll
    for (int i = 0; i < 12; ++i) acc[i] = 0.0f;

    // ---- fused steps t = 0..47 ----
#pragma unroll 1
    for (int t = 0; t < T; ++t) {
        float4 qa = *reinterpret_cast<const float4*>(xA + t * 8);
        float4 qb = *reinterpret_cast<const float4*>(xA + t * 8 + 4);
        float4 ra = *reinterpret_cast<const float4*>(xB + t * 8);
        float4 rb = *reinterpret_cast<const float4*>(xB + t * 8 + 4);
        // x splats hoisted per timestep
        u64 xpA[8], xpB[8];
        xpA[0] = pack2(qa.x); xpA[1] = pack2(qa.y); xpA[2] = pack2(qa.z); xpA[3] = pack2(qa.w);
        xpA[4] = pack2(qb.x); xpA[5] = pack2(qb.y); xpA[6] = pack2(qb.z); xpA[7] = pack2(qb.w);
        xpB[0] = pack2(ra.x); xpB[1] = pack2(ra.y); xpB[2] = pack2(ra.z); xpB[3] = pack2(ra.w);
        xpB[4] = pack2(rb.x); xpB[5] = pack2(rb.y); xpB[6] = pack2(rb.z); xpB[7] = pack2(rb.w);

        // ---- e1: my 16 units, both elements, gate-pair fma2 ----
#pragma unroll 1
        for (int uu = 0; uu < 16; ++uu) {
            int u = ub1 + uu;
            u64 bif = swp[PB1_IF + u];
            u64 bgo = swp[PB1_GO + u];
            u64 aifA = bif, agoA = bgo, aifB = bif, agoB = bgo;
            const ulonglong2* wif = reinterpret_cast<const ulonglong2*>(swp + P1IH_IF + u * 8);
            const ulonglong2* wgo = reinterpret_cast<const ulonglong2*>(swp + P1IH_GO + u * 8);
#pragma unroll
            for (int dd = 0; dd < 4; ++dd) {
                ulonglong2 qi = wif[dd];
                ulonglong2 qg = wgo[dd];
                u64 mA0 = xpA[2 * dd], mA1 = xpA[2 * dd + 1];
                u64 mB0 = xpB[2 * dd], mB1 = xpB[2 * dd + 1];
                aifA = fma2(qi.x, mA0, aifA); agoA = fma2(qg.x, mA0, agoA);
                aifB = fma2(qi.x, mB0, aifB); agoB = fma2(qg.x, mB0, agoB);
                aifA = fma2(qi.y, mA1, aifA); agoA = fma2(qg.y, mA1, agoA);
                aifB = fma2(qi.y, mB1, aifB); agoB = fma2(qg.y, mB1, agoB);
            }
            const ulonglong2* vif = reinterpret_cast<const ulonglong2*>(swp + P1HH_IF + u * 32);
            const ulonglong2* vgo = reinterpret_cast<const ulonglong2*>(swp + P1HH_GO + u * 32);
#pragma unroll
            for (int jj = 0; jj < 16; ++jj) {
                ulonglong2 qi = vif[jj];
                ulonglong2 qg = vgo[jj];
                u64 hA0 = pack2(h1A[2 * jj]);
                u64 hA1 = pack2(h1A[2 * jj + 1]);
                u64 hB0 = pack2(h1B[2 * jj]);
                u64 hB1 = pack2(h1B[2 * jj + 1]);
                aifA = fma2(qi.x, hA0, aifA); agoA = fma2(qg.x, hA0, agoA);
                aifB = fma2(qi.x, hB0, aifB); agoB = fma2(qg.x, hB0, agoB);
                aifA = fma2(qi.y, hA1, aifA); agoA = fma2(qg.y, hA1, agoA);
                aifB = fma2(qi.y, hB1, aifB); agoB = fma2(qg.y, hB1, agoB);
            }
            float hAo, hBo;
            {
                float iv, fv, gv, ov;
                unpack2(aifA, iv, fv);
                unpack2(agoA, gv, ov);
                float ig = sigf(iv), fg = sigf(fv), gg = tanha(gv), og = sigf(ov);
                float cn = fmaf(fg, c1A[uu], ig * gg);
                c1A[uu] = cn;
                hAo = og * tanha(cn);
            }
            {
                float iv, fv, gv, ov;
                unpack2(aifB, iv, fv);
                unpack2(agoB, gv, ov);
                float ig = sigf(iv), fg = sigf(fv), gg = tanha(gv), og = sigf(ov);
                float cn = fmaf(fg, c1B[uu], ig * gg);
                c1B[uu] = cn;
                hBo = og * tanha(cn);
            }
            reinterpret_cast<float2*>(swf + S_H1B + u * 64)[lane] = make_float2(hAo, hBo);
        }
        __syncthreads();
#pragma unroll
        for (int j = 0; j < 32; ++j) {
            float2 v = reinterpret_cast<const float2*>(swf + S_H1B + j * 64)[lane];
            h1A[j] = v.x;
            h1B[j] = v.y;
        }

        // ---- e2: my 4 units, both elements ----
#pragma unroll 1
        for (int uu = 0; uu < 4; ++uu) {
            int u = ub2 + uu;
            u64 bif = swp[PB2_IF + u];
            u64 bgo = swp[PB2_GO + u];
            u64 aifA = bif, agoA = bgo, aifB = bif, agoB = bgo;
            const ulonglong2* wif = reinterpret_cast<const ulonglong2*>(swp + P2IH_IF + u * 32);
            const ulonglong2* wgo = reinterpret_cast<const ulonglong2*>(swp + P2IH_GO + u * 32);
#pragma unroll
            for (int dd = 0; dd < 16; ++dd) {
                ulonglong2 qi = wif[dd];
                ulonglong2 qg = wgo[dd];
                u64 hA0 = pack2(h1A[2 * dd]);
                u64 hA1 = pack2(h1A[2 * dd + 1]);
                u64 hB0 = pack2(h1B[2 * dd]);
                u64 hB1 = pack2(h1B[2 * dd + 1]);
                aifA = fma2(qi.x, hA0, aifA); agoA = fma2(qg.x, hA0, agoA);
                aifB = fma2(qi.x, hB0, aifB); agoB = fma2(qg.x, hB0, agoB);
                aifA = fma2(qi.y, hA1, aifA); agoA = fma2(qg.y, hA1, agoA);
                aifB = fma2(qi.y, hB1, aifB); agoB = fma2(qg.y, hB1, agoB);
            }
            const ulonglong2* vif = reinterpret_cast<const ulonglong2*>(swp + P2HH_IF + u * 8);
            const ulonglong2* vgo = reinterpret_cast<const ulonglong2*>(swp + P2HH_GO + u * 8);
#pragma unroll
            for (int jj = 0; jj < 4; ++jj) {
                ulonglong2 qi = vif[jj];
                ulonglong2 qg = vgo[jj];
                u64 hA0 = pack2(h2A[2 * jj]);
                u64 hA1 = pack2(h2A[2 * jj + 1]);
                u64 hB0 = pack2(h2B[2 * jj]);
                u64 hB1 = pack2(h2B[2 * jj + 1]);
                aifA = fma2(qi.x, hA0, aifA); agoA = fma2(qg.x, hA0, agoA);
                aifB = fma2(qi.x, hB0, aifB); agoB = fma2(qg.x, hB0, agoB);
                aifA = fma2(qi.y, hA1, aifA); agoA = fma2(qg.y, hA1, agoA);
                aifB = fma2(qi.y, hB1, aifB); agoB = fma2(qg.y, hB1, agoB);
            }
            float hAo, hBo;
            {
                float iv, fv, gv, ov;
                unpack2(aifA, iv, fv);
                unpack2(agoA, gv, ov);
                float ig = sigf(iv), fg = sigf(fv), gg = tanha(gv), og = sigf(ov);
                float cn = fmaf(fg, c2A[uu], ig * gg);
                c2A[uu] = cn;
                hAo = og * tanha(cn);
            }
            {
                float iv, fv, gv, ov;
                unpack2(aifB, iv, fv);
                unpack2(agoB, gv, ov);
                float ig = sigf(iv), fg = sigf(fv), gg = tanha(gv), og = sigf(ov);
                float cn = fmaf(fg, c2B[uu], ig * gg);
                c2B[uu] = cn;
                hBo = og * tanha(cn);
            }
            reinterpret_cast<float2*>(swf + S_H2B + u * 64)[lane] = make_float2(hAo, hBo);
        }
        __syncthreads();
#pragma unroll
        for (int j = 0; j < 8; ++j) {
            float2 v = reinterpret_cast<const float2*>(swf + S_H2B + j * 64)[lane];
            h2A[j] = v.x;
            h2B[j] = v.y;
        }

        // ---- decoder: warp0 -> element A, warp1 -> element B ----
        float h2d[8];
#pragma unroll
        for (int j = 0; j < 8; ++j) h2d[j] = (half == 0) ? h2A[j] : h2B[j];
        lstm_small<1, 8>(swf + S_W3IH, swf + S_W3HH, swf + S_B3, h2d, h3, c3);
        float dv[1] = { h3[0] };
        lstm_small<2, 1>(swf + S_D1IH, swf + S_D1HH, swf + S_BD1, dv, hd1, cd1);
        lstm_small<2, 2>(swf + S_D2IH, swf + S_D2HH, swf + S_BD2, hd1, hd2, cd2);
        lstm_small<1, 2>(swf + S_D3IH, swf + S_D3HH, swf + S_BD3, hd2, hd3, cd3);
        float y = hd3[0];
        const float* gr = swf + S_G + t * 12;
#pragma unroll
        for (int j = 0; j < 12; ++j) acc[j] = fmaf(y, gr[j], acc[j]);
    }

    // ---- aux steps t = 48..59: decoder input = x[eD, t-12, 4] ----
#pragma unroll 1
    for (int t = T; t < 60; ++t) {
        float dv[1] = { xD[(t - 12) * 8 + 4] };
        lstm_small<2, 1>(swf + S_D1IH, swf + S_D1HH, swf + S_BD1, dv, hd1, cd1);
        lstm_small<2, 2>(swf + S_D2IH, swf + S_D2HH, swf + S_BD2, hd1, hd2, cd2);
        lstm_small<1, 2>(swf + S_D3IH, swf + S_D3HH, swf + S_BD3, hd2, hd3, cd3);
        float y = hd3[0];
        const float* gr = swf + S_G + t * 12;
#pragma unroll
        for (int j = 0; j < 12; ++j) acc[j] = fmaf(y, gr[j], acc[j]);
    }

    // ---- epilogue: out[eD] ----
    float r[12];
#pragma unroll
    for (int j = 0; j < 12; ++j) r[j] = acc[j] + swf[S_CB + j];
    float4* op = reinterpret_cast<float4*>(out + (size_t)eD * 12);
    op[0] = make_float4(r[0], r[1], r[2], r[3]);
    op[1] = make_float4(r[4], r[5], r[6], r[7]);
    op[2] = make_float4(r[8], r[9], r[10], r[11]);
}

extern "C" void kernel_launch(void* const* d_in, const int* in_sizes, int n_in,
                              void* d_out, int out_size) {
    (void)in_sizes; (void)n_in; (void)out_size;
    const float* x    = (const float*)d_in[0];
    const float* w1ih = (const float*)d_in[1];
    const float* w1hh = (const float*)d_in[2];
    const float* b1   = (const float*)d_in[3];
    const float* w2ih = (const float*)d_in[4];
    const float* w2hh = (const float*)d_in[5];
    const float* b2   = (const float*)d_in[6];
    const float* w3ih = (const float*)d_in[7];
    const float* w3hh = (const float*)d_in[8];
    const float* b3   = (const float*)d_in[9];
    const float* d1ih = (const float*)d_in[10];
    const float* d1hh = (const float*)d_in[11];
    const float* bd1  = (const float*)d_in[12];
    const float* d2ih = (const float*)d_in[13];
    const float* d2hh = (const float*)d_in[14];
    const float* bd2  = (const float*)d_in[15];
    const float* d3ih = (const float*)d_in[16];
    const float* d3hh = (const float*)d_in[17];
    const float* bd3  = (const float*)d_in[18];
    const float* fc1w = (const float*)d_in[19];
    const float* fc1b = (const float*)d_in[20];
    const float* fc2w = (const float*)d_in[21];
    const float* fc2b = (const float*)d_in[22];
    float* out = (float*)d_out;

    dim3 grid(BATCH / 64);   // 64 elements (2 warps) per CTA
    dim3 block(TPB);
    vd_encdec_kernel<<<grid, block>>>(
        x, w1ih, w1hh, b1, w2ih, w2hh, b2, w3ih, w3hh, b3,
        d1ih, d1hh, bd1, d2ih, d2hh, bd2, d3ih, d3hh, bd3,
        fc1w, fc1b, fc2w, fc2b, out);
}

// round 17
// speedup vs baseline: 1.4612x; 1.0521x over previous
#include <cuda_runtime.h>

// VDEncoderDecoder: stacked LSTM encoder (8->32->8->1, T=48) + decoder
// (1->2->2->1, 60 steps) + fused fc via g = fc2_w @ fc1_w.
// R16 (64 elements/CTA, 2 warps; warp owns half the units; 2 elements/lane;
// gate-pair fma.rn.f32x2 weights; tanh.approx activations) with:
//  - x splats un-hoisted (frees ~16 regs off the 255 cap)
//  - unroll 2 on e1/e2 unit loops: two units' FMA streams + activation tails
//    interleave, covering the ~50-cyc per-unit serial tail (issue was 39.9%).

#define TPB 64
static constexpr int BATCH = 32768;
static constexpr int T = 48;

typedef unsigned long long u64;

// u64 smem offsets (gate-pair weights)
static constexpr int P1IH_IF = 0;     // [u*8+d]  u=0..31   256
static constexpr int P1IH_GO = 256;   // 256
static constexpr int P1HH_IF = 512;   // [u*32+j]          1024
static constexpr int P1HH_GO = 1536;  // 1024
static constexpr int P2IH_IF = 2560;  // [u*32+d] u=0..7    256
static constexpr int P2IH_GO = 2816;  // 256
static constexpr int P2HH_IF = 3072;  // [u*8+j]            64
static constexpr int P2HH_GO = 3136;  // 64
static constexpr int PB1_IF  = 3200;  // 32
static constexpr int PB1_GO  = 3232;  // 32
static constexpr int PB2_IF  = 3264;  // 8
static constexpr int PB2_GO  = 3272;  // 8
static constexpr int U_TOTAL = 3280;  // 26240 B

// float smem offsets
static constexpr int S_W3IH = 0;     // 32
static constexpr int S_W3HH = 32;    // 4
static constexpr int S_B3   = 36;    // 4
static constexpr int S_D1IH = 40;    // 8
static constexpr int S_D1HH = 48;    // 16
static constexpr int S_BD1  = 64;    // 8
static constexpr int S_D2IH = 72;    // 16
static constexpr int S_D2HH = 88;    // 16
static constexpr int S_BD2  = 104;   // 8
static constexpr int S_D3IH = 112;   // 8
static constexpr int S_D3HH = 120;   // 4
static constexpr int S_BD3  = 124;   // 4
static constexpr int S_G    = 128;   // 720
static constexpr int S_CB   = 848;   // 12
static constexpr int S_H1B  = 860;   // 32 units x 32 lanes x 2 = 2048 (float2)
static constexpr int S_H2B  = 2908;  // 8 x 32 x 2 = 512 (float2)
static constexpr int F_TOTAL = 3420; // total smem ~39.9 KB

__device__ __forceinline__ u64 fma2(u64 a, u64 b, u64 c) {
    u64 d;
    asm("fma.rn.f32x2 %0, %1, %2, %3;" : "=l"(d) : "l"(a), "l"(b), "l"(c));
    return d;
}
__device__ __forceinline__ u64 pack2(float v) {
    u64 r;
    asm("mov.b64 %0, {%1, %1};" : "=l"(r) : "f"(v));
    return r;
}
__device__ __forceinline__ u64 pack2f(float lo, float hi) {
    u64 r;
    asm("mov.b64 %0, {%1, %2};" : "=l"(r) : "f"(lo), "f"(hi));
    return r;
}
__device__ __forceinline__ void unpack2(u64 v, float& lo, float& hi) {
    asm("mov.b64 {%0, %1}, %2;" : "=f"(lo), "=f"(hi) : "l"(v));
}

__device__ __forceinline__ float tanha(float x) {
    float y;
    asm("tanh.approx.f32 %0, %1;" : "=f"(y) : "f"(x));
    return y;
}
__device__ __forceinline__ float sigf(float x) {
    return fmaf(tanha(0.5f * x), 0.5f, 0.5f);
}

// Small scalar LSTM cell (decoder path), fully unrolled.
template<int H, int DIN>
__device__ __forceinline__ void lstm_small(
    const float* __restrict__ wih, const float* __restrict__ whh,
    const float* __restrict__ bias,
    const float (&xin)[DIN], float (&h)[H], float (&c)[H])
{
    float hn[H];
#pragma unroll
    for (int u = 0; u < H; ++u) {
        float a0 = bias[u];
        float a1 = bias[H + u];
        float a2 = bias[2 * H + u];
        float a3 = bias[3 * H + u];
#pragma unroll
        for (int d = 0; d < DIN; ++d) {
            float xv = xin[d];
            a0 = fmaf(xv, wih[u * DIN + d], a0);
            a1 = fmaf(xv, wih[(H + u) * DIN + d], a1);
            a2 = fmaf(xv, wih[(2 * H + u) * DIN + d], a2);
            a3 = fmaf(xv, wih[(3 * H + u) * DIN + d], a3);
        }
#pragma unroll
        for (int j = 0; j < H; ++j) {
            float hv = h[j];
            a0 = fmaf(hv, whh[u * H + j], a0);
            a1 = fmaf(hv, whh[(H + u) * H + j], a1);
            a2 = fmaf(hv, whh[(2 * H + u) * H + j], a2);
            a3 = fmaf(hv, whh[(3 * H + u) * H + j], a3);
        }
        float ig = sigf(a0);
        float fg = sigf(a1);
        float gg = tanha(a2);
        float og = sigf(a3);
        float cn = fmaf(fg, c[u], ig * gg);
        c[u] = cn;
        hn[u] = og * tanha(cn);
    }
#pragma unroll
    for (int u = 0; u < H; ++u) h[u] = hn[u];
}

__global__ void __launch_bounds__(TPB)
vd_encdec_kernel(
    const float* __restrict__ x,
    const float* __restrict__ w1ih, const float* __restrict__ w1hh, const float* __restrict__ b1,
    const float* __restrict__ w2ih, const float* __restrict__ w2hh, const float* __restrict__ b2,
    const float* __restrict__ w3ih, const float* __restrict__ w3hh, const float* __restrict__ b3,
    const float* __restrict__ d1ih, const float* __restrict__ d1hh, const float* __restrict__ bd1,
    const float* __restrict__ d2ih, const float* __restrict__ d2hh, const float* __restrict__ bd2,
    const float* __restrict__ d3ih, const float* __restrict__ d3hh, const float* __restrict__ bd3,
    const float* __restrict__ fc1w, const float* __restrict__ fc1b,
    const float* __restrict__ fc2w, const float* __restrict__ fc2b,
    float* __restrict__ out)
{
    __shared__ __align__(16) u64 swp[U_TOTAL];
    __shared__ __align__(16) float swf[F_TOTAL];
    const int tid = threadIdx.x;

    // ---- stage gate-pair weights ----
    for (int i = tid; i < 256; i += TPB) {
        int u = i >> 3, d = i & 7;
        swp[P1IH_IF + i] = pack2f(w1ih[u * 8 + d], w1ih[(32 + u) * 8 + d]);
        swp[P1IH_GO + i] = pack2f(w1ih[(64 + u) * 8 + d], w1ih[(96 + u) * 8 + d]);
    }
    for (int i = tid; i < 1024; i += TPB) {
        int u = i >> 5, j = i & 31;
        swp[P1HH_IF + i] = pack2f(w1hh[u * 32 + j], w1hh[(32 + u) * 32 + j]);
        swp[P1HH_GO + i] = pack2f(w1hh[(64 + u) * 32 + j], w1hh[(96 + u) * 32 + j]);
    }
    for (int i = tid; i < 256; i += TPB) {
        int u = i >> 5, d = i & 31;
        swp[P2IH_IF + i] = pack2f(w2ih[u * 32 + d], w2ih[(8 + u) * 32 + d]);
        swp[P2IH_GO + i] = pack2f(w2ih[(16 + u) * 32 + d], w2ih[(24 + u) * 32 + d]);
    }
    for (int i = tid; i < 64; i += TPB) {
        int u = i >> 3, j = i & 7;
        swp[P2HH_IF + i] = pack2f(w2hh[u * 8 + j], w2hh[(8 + u) * 8 + j]);
        swp[P2HH_GO + i] = pack2f(w2hh[(16 + u) * 8 + j], w2hh[(24 + u) * 8 + j]);
    }
    for (int i = tid; i < 32; i += TPB) {
        swp[PB1_IF + i] = pack2f(b1[i], b1[32 + i]);
        swp[PB1_GO + i] = pack2f(b1[64 + i], b1[96 + i]);
    }
    if (tid < 8) {
        swp[PB2_IF + tid] = pack2f(b2[tid], b2[8 + tid]);
        swp[PB2_GO + tid] = pack2f(b2[16 + tid], b2[24 + tid]);
    }
    // small layers + fused fc
    for (int i = tid; i < 32; i += TPB) swf[S_W3IH + i] = w3ih[i];
    if (tid < 4)  swf[S_W3HH + tid] = w3hh[tid];
    if (tid < 4)  swf[S_B3 + tid] = b3[tid];
    if (tid < 8)  swf[S_D1IH + tid] = d1ih[tid];
    if (tid < 16) swf[S_D1HH + tid] = d1hh[tid];
    if (tid < 8)  swf[S_BD1 + tid] = bd1[tid];
    if (tid < 16) swf[S_D2IH + tid] = d2ih[tid];
    if (tid < 16) swf[S_D2HH + tid] = d2hh[tid];
    if (tid < 8)  swf[S_BD2 + tid] = bd2[tid];
    if (tid < 8)  swf[S_D3IH + tid] = d3ih[tid];
    if (tid < 4)  swf[S_D3HH + tid] = d3hh[tid];
    if (tid < 4)  swf[S_BD3 + tid] = bd3[tid];
    for (int i = tid; i < 720; i += TPB) {
        int t = i / 12, j = i % 12;
        float a = 0.0f;
        for (int k = 0; k < 32; ++k)
            a = fmaf(fc2w[j * 32 + k], fc1w[k * 60 + t], a);
        swf[S_G + i] = a;
    }
    if (tid < 12) {
        float a = fc2b[tid];
        for (int k = 0; k < 32; ++k)
            a = fmaf(fc2w[tid * 32 + k], fc1b[k], a);
        swf[S_CB + tid] = a;
    }
    __syncthreads();

    const int lane = tid & 31;
    const int half = tid >> 5;
    const int base = blockIdx.x * 64;
    const int eA = base + lane;
    const int eB = base + 32 + lane;
    const int eD = base + 32 * half + lane;
    const float* xA = x + (size_t)eA * (T * 8);
    const float* xB = x + (size_t)eB * (T * 8);
    const float* xD = x + (size_t)eD * (T * 8);
    const int ub1 = half * 16;
    const int ub2 = half * 4;

    float h1A[32], h1B[32];
    float c1A[16], c1B[16];
    float h2A[8], h2B[8];
    float c2A[4], c2B[4];
    float h3[1], c3[1];
    float hd1[2], cd1[2], hd2[2], cd2[2], hd3[1], cd3[1];
    float acc[12];

#pragma unroll
    for (int i = 0; i < 32; ++i) { h1A[i] = 0.0f; h1B[i] = 0.0f; }
#pragma unroll
    for (int i = 0; i < 16; ++i) { c1A[i] = 0.0f; c1B[i] = 0.0f; }
#pragma unroll
    for (int i = 0; i < 8; ++i) { h2A[i] = 0.0f; h2B[i] = 0.0f; }
#pragma unroll
    for (int i = 0; i < 4; ++i) { c2A[i] = 0.0f; c2B[i] = 0.0f; }
    h3[0] = 0.0f; c3[0] = 0.0f;
#pragma unroll
    for (int i = 0; i < 2; ++i) { hd1[i] = 0.0f; cd1[i] = 0.0f; hd2[i] = 0.0f; cd2[i] = 0.0f; }
    hd3[0] = 0.0f; cd3[0] = 0.0f;
#pragma unroll
    for (int i = 0; i < 12; ++i) acc[i] = 0.0f;

    // ---- fused steps t = 0..47 ----
#pragma unroll 1
    for (int t = 0; t < T; ++t) {
        float4 qa = *reinterpret_cast<const float4*>(xA + t * 8);
        float4 qb = *reinterpret_cast<const float4*>(xA + t * 8 + 4);
        float4 ra = *reinterpret_cast<const float4*>(xB + t * 8);
        float4 rb = *reinterpret_cast<const float4*>(xB + t * 8 + 4);
        float xrA[8] = { qa.x, qa.y, qa.z, qa.w, qb.x, qb.y, qb.z, qb.w };
        float xrB[8] = { ra.x, ra.y, ra.z, ra.w, rb.x, rb.y, rb.z, rb.w };

        // ---- e1: my 16 units, both elements, gate-pair fma2 ----
#pragma unroll 2
        for (int uu = 0; uu < 16; ++uu) {
            int u = ub1 + uu;
            u64 bif = swp[PB1_IF + u];
            u64 bgo = swp[PB1_GO + u];
            u64 aifA = bif, agoA = bgo, aifB = bif, agoB = bgo;
            const ulonglong2* wif = reinterpret_cast<const ulonglong2*>(swp + P1IH_IF + u * 8);
            const ulonglong2* wgo = reinterpret_cast<const ulonglong2*>(swp + P1IH_GO + u * 8);
#pragma unroll
            for (int dd = 0; dd < 4; ++dd) {
                ulonglong2 qi = wif[dd];
                ulonglong2 qg = wgo[dd];
                u64 mA0 = pack2(xrA[2 * dd]);
                u64 mA1 = pack2(xrA[2 * dd + 1]);
                u64 mB0 = pack2(xrB[2 * dd]);
                u64 mB1 = pack2(xrB[2 * dd + 1]);
                aifA = fma2(qi.x, mA0, aifA); agoA = fma2(qg.x, mA0, agoA);
                aifB = fma2(qi.x, mB0, aifB); agoB = fma2(qg.x, mB0, agoB);
                aifA = fma2(qi.y, mA1, aifA); agoA = fma2(qg.y, mA1, agoA);
                aifB = fma2(qi.y, mB1, aifB); agoB = fma2(qg.y, mB1, agoB);
            }
            const ulonglong2* vif = reinterpret_cast<const ulonglong2*>(swp + P1HH_IF + u * 32);
            const ulonglong2* vgo = reinterpret_cast<const ulonglong2*>(swp + P1HH_GO + u * 32);
#pragma unroll
            for (int jj = 0; jj < 16; ++jj) {
                ulonglong2 qi = vif[jj];
                ulonglong2 qg = vgo[jj];
                u64 hA0 = pack2(h1A[2 * jj]);
                u64 hA1 = pack2(h1A[2 * jj + 1]);
                u64 hB0 = pack2(h1B[2 * jj]);
                u64 hB1 = pack2(h1B[2 * jj + 1]);
                aifA = fma2(qi.x, hA0, aifA); agoA = fma2(qg.x, hA0, agoA);
                aifB = fma2(qi.x, hB0, aifB); agoB = fma2(qg.x, hB0, agoB);
                aifA = fma2(qi.y, hA1, aifA); agoA = fma2(qg.y, hA1, agoA);
                aifB = fma2(qi.y, hB1, aifB); agoB = fma2(qg.y, hB1, agoB);
            }
            float hAo, hBo;
            {
                float iv, fv, gv, ov;
                unpack2(aifA, iv, fv);
                unpack2(agoA, gv, ov);
                float ig = sigf(iv), fg = sigf(fv), gg = tanha(gv), og = sigf(ov);
                float cn = fmaf(fg, c1A[uu], ig * gg);
                c1A[uu] = cn;
                hAo = og * tanha(cn);
            }
            {
                float iv, fv, gv, ov;
                unpack2(aifB, iv, fv);
                unpack2(agoB, gv, ov);
                float ig = sigf(iv), fg = sigf(fv), gg = tanha(gv), og = sigf(ov);
                float cn = fmaf(fg, c1B[uu], ig * gg);
                c1B[uu] = cn;
                hBo = og * tanha(cn);
            }
            reinterpret_cast<float2*>(swf + S_H1B + u * 64)[lane] = make_float2(hAo, hBo);
        }
        __syncthreads();
#pragma unroll
        for (int j = 0; j < 32; ++j) {
            float2 v = reinterpret_cast<const float2*>(swf + S_H1B + j * 64)[lane];
            h1A[j] = v.x;
            h1B[j] = v.y;
        }

        // ---- e2: my 4 units, both elements ----
#pragma unroll 2
        for (int uu = 0; uu < 4; ++uu) {
            int u = ub2 + uu;
            u64 bif = swp[PB2_IF + u];
            u64 bgo = swp[PB2_GO + u];
            u64 aifA = bif, agoA = bgo, aifB = bif, agoB = bgo;
            const ulonglong2* wif = reinterpret_cast<const ulonglong2*>(swp + P2IH_IF + u * 32);
            const ulonglong2* wgo = reinterpret_cast<const ulonglong2*>(swp + P2IH_GO + u * 32);
#pragma unroll
            for (int dd = 0; dd < 16; ++dd) {
                ulonglong2 qi = wif[dd];
                ulonglong2 qg = wgo[dd];
                u64 hA0 = pack2(h1A[2 * dd]);
                u64 hA1 = pack2(h1A[2 * dd + 1]);
                u64 hB0 = pack2(h1B[2 * dd]);
                u64 hB1 = pack2(h1B[2 * dd + 1]);
                aifA = fma2(qi.x, hA0, aifA); agoA = fma2(qg.x, hA0, agoA);
                aifB = fma2(qi.x, hB0, aifB); agoB = fma2(qg.x, hB0, agoB);
                aifA = fma2(qi.y, hA1, aifA); agoA = fma2(qg.y, hA1, agoA);
                aifB = fma2(qi.y, hB1, aifB); agoB = fma2(qg.y, hB1, agoB);
            }
            const ulonglong2* vif = reinterpret_cast<const ulonglong2*>(swp + P2HH_IF + u * 8);
            const ulonglong2* vgo = reinterpret_cast<const ulonglong2*>(swp + P2HH_GO + u * 8);
#pragma unroll
            for (int jj = 0; jj < 4; ++jj) {
                ulonglong2 qi = vif[jj];
                ulonglong2 qg = vgo[jj];
                u64 hA0 = pack2(h2A[2 * jj]);
                u64 hA1 = pack2(h2A[2 * jj + 1]);
                u64 hB0 = pack2(h2B[2 * jj]);
                u64 hB1 = pack2(h2B[2 * jj + 1]);
                aifA = fma2(qi.x, hA0, aifA); agoA = fma2(qg.x, hA0, agoA);
                aifB = fma2(qi.x, hB0, aifB); agoB = fma2(qg.x, hB0, agoB);
                aifA = fma2(qi.y, hA1, aifA); agoA = fma2(qg.y, hA1, agoA);
                aifB = fma2(qi.y, hB1, aifB); agoB = fma2(qg.y, hB1, agoB);
            }
            float hAo, hBo;
            {
                float iv, fv, gv, ov;
                unpack2(aifA, iv, fv);
                unpack2(agoA, gv, ov);
                float ig = sigf(iv), fg = sigf(fv), gg = tanha(gv), og = sigf(ov);
                float cn = fmaf(fg, c2A[uu], ig * gg);
                c2A[uu] = cn;
                hAo = og * tanha(cn);
            }
            {
                float iv, fv, gv, ov;
                unpack2(aifB, iv, fv);
                unpack2(agoB, gv, ov);
                float ig = sigf(iv), fg = sigf(fv), gg = tanha(gv), og = sigf(ov);
                float cn = fmaf(fg, c2B[uu], ig * gg);
                c2B[uu] = cn;
                hBo = og * tanha(cn);
            }
            reinterpret_cast<float2*>(swf + S_H2B + u * 64)[lane] = make_float2(hAo, hBo);
        }
        __syncthreads();
#pragma unroll
        for (int j = 0; j < 8; ++j) {
            float2 v = reinterpret_cast<const float2*>(swf + S_H2B + j * 64)[lane];
            h2A[j] = v.x;
            h2B[j] = v.y;
        }

        // ---- decoder: warp0 -> element A, warp1 -> element B ----
        float h2d[8];
#pragma unroll
        for (int j = 0; j < 8; ++j) h2d[j] = (half == 0) ? h2A[j] : h2B[j];
        lstm_small<1, 8>(swf + S_W3IH, swf + S_W3HH, swf + S_B3, h2d, h3, c3);
        float dv[1] = { h3[0] };
        lstm_small<2, 1>(swf + S_D1IH, swf + S_D1HH, swf + S_BD1, dv, hd1, cd1);
        lstm_small<2, 2>(swf + S_D2IH, swf + S_D2HH, swf + S_BD2, hd1, hd2, cd2);
        lstm_small<1, 2>(swf + S_D3IH, swf + S_D3HH, swf + S_BD3, hd2, hd3, cd3);
        float y = hd3[0];
        const float* gr = swf + S_G + t * 12;
#pragma unroll
        for (int j = 0; j < 12; ++j) acc[j] = fmaf(y, gr[j], acc[j]);
    }

    // ---- aux steps t = 48..59: decoder input = x[eD, t-12, 4] ----
#pragma unroll 1
    for (int t = T; t < 60; ++t) {
        float dv[1] = { xD[(t - 12) * 8 + 4] };
        lstm_small<2, 1>(swf + S_D1IH, swf + S_D1HH, swf + S_BD1, dv, hd1, cd1);
        lstm_small<2, 2>(swf + S_D2IH, swf + S_D2HH, swf + S_BD2, hd1, hd2, cd2);
        lstm_small<1, 2>(swf + S_D3IH, swf + S_D3HH, swf + S_BD3, hd2, hd3, cd3);
        float y = hd3[0];
        const float* gr = swf + S_G + t * 12;
#pragma unroll
        for (int j = 0; j < 12; ++j) acc[j] = fmaf(y, gr[j], acc[j]);
    }

    // ---- epilogue: out[eD] ----
    float r[12];
#pragma unroll
    for (int j = 0; j < 12; ++j) r[j] = acc[j] + swf[S_CB + j];
    float4* op = reinterpret_cast<float4*>(out + (size_t)eD * 12);
    op[0] = make_float4(r[0], r[1], r[2], r[3]);
    op[1] = make_float4(r[4], r[5], r[6], r[7]);
    op[2] = make_float4(r[8], r[9], r[10], r[11]);
}

extern "C" void kernel_launch(void* const* d_in, const int* in_sizes, int n_in,
                              void* d_out, int out_size) {
    (void)in_sizes; (void)n_in; (void)out_size;
    const float* x    = (const float*)d_in[0];
    const float* w1ih = (const float*)d_in[1];
    const float* w1hh = (const float*)d_in[2];
    const float* b1   = (const float*)d_in[3];
    const float* w2ih = (const float*)d_in[4];
    const float* w2hh = (const float*)d_in[5];
    const float* b2   = (const float*)d_in[6];
    const float* w3ih = (const float*)d_in[7];
    const float* w3hh = (const float*)d_in[8];
    const float* b3   = (const float*)d_in[9];
    const float* d1ih = (const float*)d_in[10];
    const float* d1hh = (const float*)d_in[11];
    const float* bd1  = (const float*)d_in[12];
    const float* d2ih = (const float*)d_in[13];
    const float* d2hh = (const float*)d_in[14];
    const float* bd2  = (const float*)d_in[15];
    const float* d3ih = (const float*)d_in[16];
    const float* d3hh = (const float*)d_in[17];
    const float* bd3  = (const float*)d_in[18];
    const float* fc1w = (const float*)d_in[19];
    const float* fc1b = (const float*)d_in[20];
    const float* fc2w = (const float*)d_in[21];
    const float* fc2b = (const float*)d_in[22];
    float* out = (float*)d_out;

    dim3 grid(BATCH / 64);   // 64 elements (2 warps) per CTA
    dim3 block(TPB);
    vd_encdec_kernel<<<grid, block>>>(
        x, w1ih, w1hh, b1, w2ih, w2hh, b2, w3ih, w3hh, b3,
        d1ih, d1hh, bd1, d2ih, d2hh, bd2, d3ih, d3hh, bd3,
        fc1w, fc1b, fc2w, fc2b, out);
}